// round 1
// baseline (speedup 1.0000x reference)
#include <cuda_runtime.h>
#include <mma.h>
using namespace nvcuda;

// Problem constants
#define BATCH 16
#define SEQ   1024      // M == N == 1024
#define DT    1024
#define HID   512
#define NEG_INF_F (-1.0e9f)
static __device__ __host__ constexpr float INV_SQRT = 0.03125f;  // 1/sqrt(1024)

static constexpr long ELEM1 = 16LL * 1024 * 1024;  // one (B, 1024, 1024) fp32 tensor

// Scratch: 8 big tensors + pools + gate values
__device__ float g_scr[ELEM1 * 8 + 2 * BATCH * DT + 64];

// ---------------------------------------------------------------------------
// TF32 WMMA GEMM: C[M,N] = A[M,K] * op(B) (+ bias)
//   BT=true : B is (N x K) row-major, C = A * B^T   (x@W^T, Q@K^T)
//   BT=false: B is (K x N) row-major, C = A * B     (attn @ V)
// Batched via blockIdx.z with element strides sA/sB/sC.
// Block tile 128x128x16, 8 warps (4x2), warp tile 32x64 (2x4 m16n16k8 frags).
// ---------------------------------------------------------------------------
template <bool BT, bool BIAS>
__global__ __launch_bounds__(256)
void gemm_tf32(const float* __restrict__ A, const float* __restrict__ Bm,
               const float* __restrict__ bias, float* __restrict__ C,
               int M, int N, int K, long sA, long sB, long sC)
{
    __shared__ __align__(32) float As[128][24];     // (m,k), ld=24
    __shared__ __align__(32) float Bbuf[3072];      // BT: [n][k] ld=24 ; else [k][n] ld=136
    __shared__ __align__(32) float Cst[8][16][20];  // per-warp epilogue staging

    long zb = blockIdx.z;
    A  += zb * sA;
    Bm += zb * sB;
    C  += zb * sC;

    const int m0   = blockIdx.y * 128;
    const int n0   = blockIdx.x * 128;
    const int tid  = threadIdx.x;
    const int warp = tid >> 5;
    const int lane = tid & 31;
    const int wm   = warp & 3;   // 0..3 -> m offset 32*wm
    const int wn   = warp >> 2;  // 0..1 -> n offset 64*wn

    wmma::fragment<wmma::accumulator, 16, 16, 8, float> acc[2][4];
#pragma unroll
    for (int mi = 0; mi < 2; mi++)
#pragma unroll
        for (int ni = 0; ni < 4; ni++)
            wmma::fill_fragment(acc[mi][ni], 0.0f);

    for (int k0 = 0; k0 < K; k0 += 16) {
        // A tile: 128x16 floats = 512 float4, 2 per thread
#pragma unroll
        for (int i = 0; i < 2; i++) {
            int f = tid + i * 256;
            int r = f >> 2, kq = f & 3;
            float4 v = *reinterpret_cast<const float4*>(A + (long)(m0 + r) * K + (k0 + kq * 4));
            *reinterpret_cast<float4*>(&As[r][kq * 4]) = v;
        }
        if (BT) {
            // B tile: rows n0..n0+127, k chunk 16 -> [n][k]
#pragma unroll
            for (int i = 0; i < 2; i++) {
                int f = tid + i * 256;
                int r = f >> 2, kq = f & 3;
                float4 v = *reinterpret_cast<const float4*>(Bm + (long)(n0 + r) * K + (k0 + kq * 4));
                *reinterpret_cast<float4*>(&Bbuf[r * 24 + kq * 4]) = v;
            }
        } else {
            // B tile: rows k0..k0+15, cols n0..n0+127 -> [k][n]
#pragma unroll
            for (int i = 0; i < 2; i++) {
                int f = tid + i * 256;
                int r = f >> 5, nq = f & 31;
                float4 v = *reinterpret_cast<const float4*>(Bm + (long)(k0 + r) * N + (n0 + nq * 4));
                *reinterpret_cast<float4*>(&Bbuf[r * 136 + nq * 4]) = v;
            }
        }
        __syncthreads();

#pragma unroll
        for (int kk = 0; kk < 16; kk += 8) {
            wmma::fragment<wmma::matrix_a, 16, 16, 8, wmma::precision::tf32, wmma::row_major> af[2];
#pragma unroll
            for (int mi = 0; mi < 2; mi++) {
                wmma::load_matrix_sync(af[mi], &As[wm * 32 + mi * 16][kk], 24);
#pragma unroll
                for (int e = 0; e < af[mi].num_elements; e++)
                    af[mi].x[e] = wmma::__float_to_tf32(af[mi].x[e]);
            }
            if (BT) {
                wmma::fragment<wmma::matrix_b, 16, 16, 8, wmma::precision::tf32, wmma::col_major> bf[4];
#pragma unroll
                for (int ni = 0; ni < 4; ni++) {
                    wmma::load_matrix_sync(bf[ni], &Bbuf[(wn * 64 + ni * 16) * 24 + kk], 24);
#pragma unroll
                    for (int e = 0; e < bf[ni].num_elements; e++)
                        bf[ni].x[e] = wmma::__float_to_tf32(bf[ni].x[e]);
                }
#pragma unroll
                for (int mi = 0; mi < 2; mi++)
#pragma unroll
                    for (int ni = 0; ni < 4; ni++)
                        wmma::mma_sync(acc[mi][ni], af[mi], bf[ni], acc[mi][ni]);
            } else {
                wmma::fragment<wmma::matrix_b, 16, 16, 8, wmma::precision::tf32, wmma::row_major> bf[4];
#pragma unroll
                for (int ni = 0; ni < 4; ni++) {
                    wmma::load_matrix_sync(bf[ni], &Bbuf[kk * 136 + wn * 64 + ni * 16], 136);
#pragma unroll
                    for (int e = 0; e < bf[ni].num_elements; e++)
                        bf[ni].x[e] = wmma::__float_to_tf32(bf[ni].x[e]);
                }
#pragma unroll
                for (int mi = 0; mi < 2; mi++)
#pragma unroll
                    for (int ni = 0; ni < 4; ni++)
                        wmma::mma_sync(acc[mi][ni], af[mi], bf[ni], acc[mi][ni]);
            }
        }
        __syncthreads();
    }

    // Epilogue via per-warp staging (bias add)
#pragma unroll
    for (int mi = 0; mi < 2; mi++) {
#pragma unroll
        for (int ni = 0; ni < 4; ni++) {
            wmma::store_matrix_sync(&Cst[warp][0][0], acc[mi][ni], 20, wmma::mem_row_major);
            __syncwarp();
            int r  = lane >> 1;
            int c0 = (lane & 1) * 8;
            int gm = m0 + wm * 32 + mi * 16 + r;
            int gn = n0 + wn * 64 + ni * 16 + c0;
            float* dst = C + (long)gm * N + gn;
#pragma unroll
            for (int j = 0; j < 8; j++) {
                float v = Cst[warp][r][c0 + j];
                if (BIAS) v += bias[gn + j];
                dst[j] = v;
            }
            __syncwarp();
        }
    }
}

// ---------------------------------------------------------------------------
// Mean-pool over sequence dim: dst[b,d] = mean_m src[b,m,d]
// grid (DT/256, B), block 256
// ---------------------------------------------------------------------------
__global__ void pool_kernel(const float* __restrict__ src, float* __restrict__ dst)
{
    int b = blockIdx.y;
    int d = blockIdx.x * 256 + threadIdx.x;
    const float* p = src + ((long)b << 20) + d;
    float s = 0.f;
#pragma unroll 8
    for (int m = 0; m < SEQ; m++) s += p[(long)m << 10];
    dst[b * DT + d] = s * (1.0f / 1024.0f);
}

// ---------------------------------------------------------------------------
// Gate FFN: l[b] = sigmoid(w2 . relu(W1 [vp;tp] + b1) + b2). 16 blocks x 512 thr
// ---------------------------------------------------------------------------
__global__ void ffn_kernel(const float* __restrict__ poolV, const float* __restrict__ poolT,
                           const float* __restrict__ w1, const float* __restrict__ b1,
                           const float* __restrict__ w2, const float* __restrict__ b2,
                           float* __restrict__ lout)
{
    __shared__ float x[2 * DT];
    __shared__ float red[HID];
    int b = blockIdx.x, t = threadIdx.x;
    for (int i = t; i < 2 * DT; i += HID)
        x[i] = (i < DT) ? poolV[b * DT + i] : poolT[b * DT + (i - DT)];
    __syncthreads();

    float acc = b1[t];
    const float* wr = w1 + (long)t * (2 * DT);
#pragma unroll 8
    for (int k = 0; k < 2 * DT; k++) acc += wr[k] * x[k];
    float h = fmaxf(acc, 0.0f);
    red[t] = h * w2[t];
    __syncthreads();
    for (int s = HID / 2; s > 0; s >>= 1) {
        if (t < s) red[t] += red[t + s];
        __syncthreads();
    }
    if (t == 0) lout[b] = 1.0f / (1.0f + expf(-(red[0] + b2[0])));
}

// ---------------------------------------------------------------------------
// Row reductions (256 threads, 4 elems/thread)
// ---------------------------------------------------------------------------
__device__ __forceinline__ float block_max(float v, float* red)
{
    int t = threadIdx.x;
    red[t] = v; __syncthreads();
    for (int s = 128; s > 0; s >>= 1) {
        if (t < s) red[t] = fmaxf(red[t], red[t + s]);
        __syncthreads();
    }
    float r = red[0]; __syncthreads();
    return r;
}
__device__ __forceinline__ float block_sum(float v, float* red)
{
    int t = threadIdx.x;
    red[t] = v; __syncthreads();
    for (int s = 128; s > 0; s >>= 1) {
        if (t < s) red[t] += red[t + s];
        __syncthreads();
    }
    float r = red[0]; __syncthreads();
    return r;
}

// Mask from sim: Mmask = softmax(sim*inv) >= l[b]. grid(1024, B), block 256
__global__ void mask_kernel(const float* __restrict__ S, const float* __restrict__ lv,
                            float* __restrict__ maskO)
{
    __shared__ float red[256];
    int t = threadIdx.x;
    long row = (long)blockIdx.y * SEQ + blockIdx.x;
    const float* p = S + row * SEQ;
    float x[4];
    float mx = -3.4e38f;
#pragma unroll
    for (int i = 0; i < 4; i++) {
        x[i] = p[t + i * 256] * INV_SQRT;
        mx = fmaxf(mx, x[i]);
    }
    mx = block_max(mx, red);
    float s = 0.f;
#pragma unroll
    for (int i = 0; i < 4; i++) s += expf(x[i] - mx);
    s = block_sum(s, red);
    float l = lv[blockIdx.y];
    float* o = maskO + row * SEQ;
#pragma unroll
    for (int i = 0; i < 4; i++)
        o[t + i * 256] = ((expf(x[i] - mx) / s) >= l) ? 1.0f : 0.0f;
}

// Masked softmax, in place on scores. grid(1024, B), block 256
__global__ void msoftmax_kernel(float* __restrict__ S, const float* __restrict__ maskM)
{
    __shared__ float red[256];
    int t = threadIdx.x;
    long row = (long)blockIdx.y * SEQ + blockIdx.x;
    float* p = S + row * SEQ;
    const float* mk = maskM + row * SEQ;
    float x[4];
    float mx = -3.4e38f;
#pragma unroll
    for (int i = 0; i < 4; i++) {
        int idx = t + i * 256;
        x[i] = (mk[idx] != 0.0f) ? p[idx] * INV_SQRT : NEG_INF_F;
        mx = fmaxf(mx, x[i]);
    }
    mx = block_max(mx, red);
    float s = 0.f;
#pragma unroll
    for (int i = 0; i < 4; i++) s += expf(x[i] - mx);
    s = block_sum(s, red);
#pragma unroll
    for (int i = 0; i < 4; i++)
        p[t + i * 256] = expf(x[i] - mx) / s;
}

// Transpose mask per batch: out[b,n,m] = in[b,m,n]. grid(32,32,B), block(32,32)
__global__ void transpose_kernel(const float* __restrict__ in, float* __restrict__ out)
{
    __shared__ float tile[32][33];
    long base = (long)blockIdx.z << 20;
    int m = blockIdx.y * 32 + threadIdx.y;
    int n = blockIdx.x * 32 + threadIdx.x;
    tile[threadIdx.y][threadIdx.x] = in[base + (long)m * SEQ + n];
    __syncthreads();
    int n2 = blockIdx.x * 32 + threadIdx.y;
    int m2 = blockIdx.y * 32 + threadIdx.x;
    out[base + (long)n2 * SEQ + m2] = tile[threadIdx.x][threadIdx.y];
}

// ---------------------------------------------------------------------------
extern "C" void kernel_launch(void* const* d_in, const int* in_sizes, int n_in,
                              void* d_out, int out_size)
{
    (void)in_sizes; (void)n_in; (void)out_size;

    const float* oV     = (const float*)d_in[0];
    const float* oT     = (const float*)d_in[1];
    const float* Wq_v_w = (const float*)d_in[2];
    const float* Wq_v_b = (const float*)d_in[3];
    const float* Wk_t_w = (const float*)d_in[4];
    const float* Wk_t_b = (const float*)d_in[5];
    const float* Wv_t_w = (const float*)d_in[6];
    const float* Wv_t_b = (const float*)d_in[7];
    const float* Wq_t_w = (const float*)d_in[8];
    const float* Wq_t_b = (const float*)d_in[9];
    const float* Wk_v_w = (const float*)d_in[10];
    const float* Wk_v_b = (const float*)d_in[11];
    const float* Wv_v_w = (const float*)d_in[12];
    const float* Wv_v_b = (const float*)d_in[13];
    const float* ffn1_w = (const float*)d_in[14];
    const float* ffn1_b = (const float*)d_in[15];
    const float* ffn2_w = (const float*)d_in[16];
    const float* ffn2_b = (const float*)d_in[17];

    float* out_vt = (float*)d_out;             // (B, M, DT)
    float* out_tv = out_vt + ELEM1;            // (B, N, DT)
    float* maskO  = out_vt + 2 * ELEM1;        // (B, M, N) float mask

    static float* scr = nullptr;
    if (!scr) cudaGetSymbolAddress((void**)&scr, g_scr);

    float* Qv    = scr + 0 * ELEM1;
    float* Kv    = scr + 1 * ELEM1;
    float* Vv    = scr + 2 * ELEM1;
    float* Qt    = scr + 3 * ELEM1;
    float* Kt    = scr + 4 * ELEM1;
    float* Vt    = scr + 5 * ELEM1;
    float* Ssc   = scr + 6 * ELEM1;
    float* maskT = scr + 7 * ELEM1;
    float* poolV = scr + 8 * ELEM1;
    float* poolT = poolV + BATCH * DT;
    float* lv    = poolT + BATCH * DT;

    const long S1 = (long)SEQ * SEQ;  // per-batch stride (1M elems)

    // 1) pools + gate
    pool_kernel<<<dim3(4, BATCH), 256>>>(oV, poolV);
    pool_kernel<<<dim3(4, BATCH), 256>>>(oT, poolT);
    ffn_kernel<<<BATCH, HID>>>(poolV, poolT, ffn1_w, ffn1_b, ffn2_w, ffn2_b, lv);

    // 2) projections (X @ W^T + b), M = B*SEQ = 16384 rows
    dim3 gp(8, 128, 1);
    gemm_tf32<true, true><<<gp, 256>>>(oV, Wq_v_w, Wq_v_b, Qv, BATCH * SEQ, DT, DT, 0, 0, 0);
    gemm_tf32<true, true><<<gp, 256>>>(oT, Wk_t_w, Wk_t_b, Kt, BATCH * SEQ, DT, DT, 0, 0, 0);
    gemm_tf32<true, true><<<gp, 256>>>(oT, Wv_t_w, Wv_t_b, Vt, BATCH * SEQ, DT, DT, 0, 0, 0);
    gemm_tf32<true, true><<<gp, 256>>>(oT, Wq_t_w, Wq_t_b, Qt, BATCH * SEQ, DT, DT, 0, 0, 0);
    gemm_tf32<true, true><<<gp, 256>>>(oV, Wk_v_w, Wk_v_b, Kv, BATCH * SEQ, DT, DT, 0, 0, 0);
    gemm_tf32<true, true><<<gp, 256>>>(oV, Wv_v_w, Wv_v_b, Vv, BATCH * SEQ, DT, DT, 0, 0, 0);

    dim3 gb(8, 8, BATCH);

    // 3) sim = oV @ oT^T (batched), then mask + maskT
    gemm_tf32<true, false><<<gb, 256>>>(oV, oT, nullptr, Ssc, SEQ, SEQ, DT, S1, S1, S1);
    mask_kernel<<<dim3(SEQ, BATCH), 256>>>(Ssc, lv, maskO);
    transpose_kernel<<<dim3(32, 32, BATCH), dim3(32, 32)>>>(maskO, maskT);

    // 4) V->T attention
    gemm_tf32<true, false><<<gb, 256>>>(Qv, Kt, nullptr, Ssc, SEQ, SEQ, DT, S1, S1, S1);
    msoftmax_kernel<<<dim3(SEQ, BATCH), 256>>>(Ssc, maskO);
    gemm_tf32<false, false><<<gb, 256>>>(Ssc, Vt, nullptr, out_vt, SEQ, DT, SEQ, S1, S1, S1);

    // 5) T->V attention (transposed mask)
    gemm_tf32<true, false><<<gb, 256>>>(Qt, Kv, nullptr, Ssc, SEQ, SEQ, DT, S1, S1, S1);
    msoftmax_kernel<<<dim3(SEQ, BATCH), 256>>>(Ssc, maskT);
    gemm_tf32<false, false><<<gb, 256>>>(Ssc, Vv, nullptr, out_tv, SEQ, DT, SEQ, S1, S1, S1);
}

// round 3
// speedup vs baseline: 1.0824x; 1.0824x over previous
#include <cuda_runtime.h>
#include <mma.h>
#include <cstdint>
using namespace nvcuda;

// Problem constants
#define BATCH 16
#define SEQ   1024
#define DT    1024
#define HID   512
#define NEG_INF_F (-1.0e9f)
static __device__ __host__ constexpr float INV_SQRT = 0.03125f;  // 1/sqrt(1024)

static constexpr long ELEM1 = 16LL * 1024 * 1024;

__device__ __align__(1024) float g_scr[ELEM1 * 8 + 2 * BATCH * DT + 64];

// ---------------------------------------------------------------------------
// cp.async helpers
// ---------------------------------------------------------------------------
__device__ __forceinline__ uint32_t smem_u32(const void* p) {
    uint32_t a;
    asm("{ .reg .u64 t; cvta.to.shared.u64 t, %1; cvt.u32.u64 %0, t; }" : "=r"(a) : "l"(p));
    return a;
}
__device__ __forceinline__ void cp_async16(uint32_t saddr, const void* gaddr) {
    asm volatile("cp.async.cg.shared.global [%0], [%1], 16;" :: "r"(saddr), "l"(gaddr));
}
__device__ __forceinline__ void cp_commit() {
    asm volatile("cp.async.commit_group;" ::: "memory");
}
template <int N>
__device__ __forceinline__ void cp_wait() {
    asm volatile("cp.async.wait_group %0;" :: "n"(N) : "memory");
}

// ---------------------------------------------------------------------------
// TF32 WMMA GEMM, 3-stage cp.async pipeline.
//   C[M,N] = A[M,K] * op(B) (+ bias)
//   BT=true : B is (N x K) row-major, C = A * B^T
//   BT=false: B is (K x N) row-major, C = A * B
// Block tile 128x128x32, 8 warps (4x2), warp tile 32x64 (2x4 m16n16k8 frags).
// Dynamic SMEM: 3 stages x (A 128x36 + B 128x36) floats = 110,592 B.
// ---------------------------------------------------------------------------
static constexpr int KT      = 32;               // K per stage
static constexpr int STAGES  = 3;
static constexpr int A_F     = 128 * 36;         // floats per A stage (pitch 36)
static constexpr int B_F     = 128 * 36;         // >= 32*136 for BT=false too
static constexpr int STAGE_F = A_F + B_F;        // 9216 floats
static constexpr int GEMM_SMEM = STAGES * STAGE_F * 4;  // 110,592 bytes

template <bool BT, bool BIAS>
__global__ __launch_bounds__(256, 2)
void gemm_tf32(const float* __restrict__ A, const float* __restrict__ Bm,
               const float* __restrict__ bias, float* __restrict__ C,
               int M, int N, int K, long sA, long sB, long sC)
{
    extern __shared__ float dyn[];

    long zb = blockIdx.z;
    A  += zb * sA;
    Bm += zb * sB;
    C  += zb * sC;

    const int m0   = blockIdx.y * 128;
    const int n0   = blockIdx.x * 128;
    const int tid  = threadIdx.x;
    const int warp = tid >> 5;
    const int lane = tid & 31;
    const int wm   = warp & 3;
    const int wn   = warp >> 2;

    const int NKT = K / KT;

    // per-thread load coords (4 float4 per tile side)
    // A / B(BT): r = f>>3, kq = f&7   (128 rows x 8 float4)
    // B(!BT)   : r = f>>5, nq = f&31  (32 rows x 32 float4)
    uint32_t dynb = smem_u32(dyn);

    auto issue_stage = [&](int kt, int slot) {
        const int k0 = kt * KT;
        uint32_t sa = dynb + (slot * STAGE_F) * 4;
        uint32_t sb = dynb + (slot * STAGE_F + A_F) * 4;
#pragma unroll
        for (int i = 0; i < 4; i++) {
            int f = tid + i * 256;
            int r = f >> 3, kq = f & 7;
            cp_async16(sa + (r * 36 + kq * 4) * 4,
                       A + (long)(m0 + r) * K + (k0 + kq * 4));
        }
        if (BT) {
#pragma unroll
            for (int i = 0; i < 4; i++) {
                int f = tid + i * 256;
                int r = f >> 3, kq = f & 7;
                cp_async16(sb + (r * 36 + kq * 4) * 4,
                           Bm + (long)(n0 + r) * K + (k0 + kq * 4));
            }
        } else {
#pragma unroll
            for (int i = 0; i < 4; i++) {
                int f = tid + i * 256;
                int r = f >> 5, nq = f & 31;
                cp_async16(sb + (r * 136 + nq * 4) * 4,
                           Bm + (long)(k0 + r) * N + (n0 + nq * 4));
            }
        }
        cp_commit();
    };

    wmma::fragment<wmma::accumulator, 16, 16, 8, float> acc[2][4];
#pragma unroll
    for (int mi = 0; mi < 2; mi++)
#pragma unroll
        for (int ni = 0; ni < 4; ni++)
            wmma::fill_fragment(acc[mi][ni], 0.0f);

    // prologue: stages 0, 1
    issue_stage(0, 0);
    issue_stage(1, 1);

    for (int kt = 0; kt < NKT; kt++) {
        cp_wait<STAGES - 2>();
        __syncthreads();

        // issue next stage into the slot freed by iteration kt-1
        int nk = kt + STAGES - 1;
        if (nk < NKT) issue_stage(nk, nk % STAGES);
        else          cp_commit();          // keep group count consistent

        const int slot = kt % STAGES;
        const float* As = dyn + slot * STAGE_F;
        const float* Bs = dyn + slot * STAGE_F + A_F;

#pragma unroll
        for (int kk = 0; kk < KT; kk += 8) {
            wmma::fragment<wmma::matrix_a, 16, 16, 8, wmma::precision::tf32, wmma::row_major> af[2];
#pragma unroll
            for (int mi = 0; mi < 2; mi++) {
                wmma::load_matrix_sync(af[mi], &As[(wm * 32 + mi * 16) * 36 + kk], 36);
#pragma unroll
                for (int e = 0; e < af[mi].num_elements; e++)
                    af[mi].x[e] = wmma::__float_to_tf32(af[mi].x[e]);
            }
            if (BT) {
                wmma::fragment<wmma::matrix_b, 16, 16, 8, wmma::precision::tf32, wmma::col_major> bf[4];
#pragma unroll
                for (int ni = 0; ni < 4; ni++) {
                    wmma::load_matrix_sync(bf[ni], &Bs[(wn * 64 + ni * 16) * 36 + kk], 36);
#pragma unroll
                    for (int e = 0; e < bf[ni].num_elements; e++)
                        bf[ni].x[e] = wmma::__float_to_tf32(bf[ni].x[e]);
                }
#pragma unroll
                for (int mi = 0; mi < 2; mi++)
#pragma unroll
                    for (int ni = 0; ni < 4; ni++)
                        wmma::mma_sync(acc[mi][ni], af[mi], bf[ni], acc[mi][ni]);
            } else {
                wmma::fragment<wmma::matrix_b, 16, 16, 8, wmma::precision::tf32, wmma::row_major> bf[4];
#pragma unroll
                for (int ni = 0; ni < 4; ni++) {
                    wmma::load_matrix_sync(bf[ni], &Bs[kk * 136 + wn * 64 + ni * 16], 136);
#pragma unroll
                    for (int e = 0; e < bf[ni].num_elements; e++)
                        bf[ni].x[e] = wmma::__float_to_tf32(bf[ni].x[e]);
                }
#pragma unroll
                for (int mi = 0; mi < 2; mi++)
#pragma unroll
                    for (int ni = 0; ni < 4; ni++)
                        wmma::mma_sync(acc[mi][ni], af[mi], bf[ni], acc[mi][ni]);
            }
        }
        __syncthreads();
    }
    cp_wait<0>();
    __syncthreads();   // all compute done; stage memory reusable for epilogue

    // epilogue: per-warp staging in (reused) dynamic smem, pitch 20
    float* Cst = dyn + warp * 16 * 20;
#pragma unroll
    for (int mi = 0; mi < 2; mi++) {
#pragma unroll
        for (int ni = 0; ni < 4; ni++) {
            wmma::store_matrix_sync(Cst, acc[mi][ni], 20, wmma::mem_row_major);
            __syncwarp();
            int r  = lane >> 1;
            int c0 = (lane & 1) * 8;
            int gm = m0 + wm * 32 + mi * 16 + r;
            int gn = n0 + wn * 64 + ni * 16 + c0;
            float* dst = C + (long)gm * N + gn;
#pragma unroll
            for (int j = 0; j < 8; j++) {
                float v = Cst[r * 20 + c0 + j];
                if (BIAS) v += bias[gn + j];
                dst[j] = v;
            }
            __syncwarp();
        }
    }
}

// ---------------------------------------------------------------------------
// Elementwise kernels (unchanged, known correct)
// ---------------------------------------------------------------------------
__global__ void pool_kernel(const float* __restrict__ src, float* __restrict__ dst)
{
    int b = blockIdx.y;
    int d = blockIdx.x * 256 + threadIdx.x;
    const float* p = src + ((long)b << 20) + d;
    float s = 0.f;
#pragma unroll 8
    for (int m = 0; m < SEQ; m++) s += p[(long)m << 10];
    dst[b * DT + d] = s * (1.0f / 1024.0f);
}

__global__ void ffn_kernel(const float* __restrict__ poolV, const float* __restrict__ poolT,
                           const float* __restrict__ w1, const float* __restrict__ b1,
                           const float* __restrict__ w2, const float* __restrict__ b2,
                           float* __restrict__ lout)
{
    __shared__ float x[2 * DT];
    __shared__ float red[HID];
    int b = blockIdx.x, t = threadIdx.x;
    for (int i = t; i < 2 * DT; i += HID)
        x[i] = (i < DT) ? poolV[b * DT + i] : poolT[b * DT + (i - DT)];
    __syncthreads();
    float acc = b1[t];
    const float* wr = w1 + (long)t * (2 * DT);
#pragma unroll 8
    for (int k = 0; k < 2 * DT; k++) acc += wr[k] * x[k];
    float h = fmaxf(acc, 0.0f);
    red[t] = h * w2[t];
    __syncthreads();
    for (int s = HID / 2; s > 0; s >>= 1) {
        if (t < s) red[t] += red[t + s];
        __syncthreads();
    }
    if (t == 0) lout[b] = 1.0f / (1.0f + expf(-(red[0] + b2[0])));
}

__device__ __forceinline__ float block_max(float v, float* red)
{
    int t = threadIdx.x;
    red[t] = v; __syncthreads();
    for (int s = 128; s > 0; s >>= 1) {
        if (t < s) red[t] = fmaxf(red[t], red[t + s]);
        __syncthreads();
    }
    float r = red[0]; __syncthreads();
    return r;
}
__device__ __forceinline__ float block_sum(float v, float* red)
{
    int t = threadIdx.x;
    red[t] = v; __syncthreads();
    for (int s = 128; s > 0; s >>= 1) {
        if (t < s) red[t] += red[t + s];
        __syncthreads();
    }
    float r = red[0]; __syncthreads();
    return r;
}

__global__ void mask_kernel(const float* __restrict__ S, const float* __restrict__ lv,
                            float* __restrict__ maskO)
{
    __shared__ float red[256];
    int t = threadIdx.x;
    long row = (long)blockIdx.y * SEQ + blockIdx.x;
    const float* p = S + row * SEQ;
    float x[4];
    float mx = -3.4e38f;
#pragma unroll
    for (int i = 0; i < 4; i++) {
        x[i] = p[t + i * 256] * INV_SQRT;
        mx = fmaxf(mx, x[i]);
    }
    mx = block_max(mx, red);
    float s = 0.f;
#pragma unroll
    for (int i = 0; i < 4; i++) s += expf(x[i] - mx);
    s = block_sum(s, red);
    float l = lv[blockIdx.y];
    float* o = maskO + row * SEQ;
#pragma unroll
    for (int i = 0; i < 4; i++)
        o[t + i * 256] = ((expf(x[i] - mx) / s) >= l) ? 1.0f : 0.0f;
}

__global__ void msoftmax_kernel(float* __restrict__ S, const float* __restrict__ maskM)
{
    __shared__ float red[256];
    int t = threadIdx.x;
    long row = (long)blockIdx.y * SEQ + blockIdx.x;
    float* p = S + row * SEQ;
    const float* mk = maskM + row * SEQ;
    float x[4];
    float mx = -3.4e38f;
#pragma unroll
    for (int i = 0; i < 4; i++) {
        int idx = t + i * 256;
        x[i] = (mk[idx] != 0.0f) ? p[idx] * INV_SQRT : NEG_INF_F;
        mx = fmaxf(mx, x[i]);
    }
    mx = block_max(mx, red);
    float s = 0.f;
#pragma unroll
    for (int i = 0; i < 4; i++) s += expf(x[i] - mx);
    s = block_sum(s, red);
#pragma unroll
    for (int i = 0; i < 4; i++)
        p[t + i * 256] = expf(x[i] - mx) / s;
}

__global__ void transpose_kernel(const float* __restrict__ in, float* __restrict__ out)
{
    __shared__ float tile[32][33];
    long base = (long)blockIdx.z << 20;
    int m = blockIdx.y * 32 + threadIdx.y;
    int n = blockIdx.x * 32 + threadIdx.x;
    tile[threadIdx.y][threadIdx.x] = in[base + (long)m * SEQ + n];
    __syncthreads();
    int n2 = blockIdx.x * 32 + threadIdx.y;
    int m2 = blockIdx.y * 32 + threadIdx.x;
    out[base + (long)n2 * SEQ + m2] = tile[threadIdx.x][threadIdx.y];
}

// ---------------------------------------------------------------------------
extern "C" void kernel_launch(void* const* d_in, const int* in_sizes, int n_in,
                              void* d_out, int out_size)
{
    (void)in_sizes; (void)n_in; (void)out_size;

    const float* oV     = (const float*)d_in[0];
    const float* oT     = (const float*)d_in[1];
    const float* Wq_v_w = (const float*)d_in[2];
    const float* Wq_v_b = (const float*)d_in[3];
    const float* Wk_t_w = (const float*)d_in[4];
    const float* Wk_t_b = (const float*)d_in[5];
    const float* Wv_t_w = (const float*)d_in[6];
    const float* Wv_t_b = (const float*)d_in[7];
    const float* Wq_t_w = (const float*)d_in[8];
    const float* Wq_t_b = (const float*)d_in[9];
    const float* Wk_v_w = (const float*)d_in[10];
    const float* Wk_v_b = (const float*)d_in[11];
    const float* Wv_v_w = (const float*)d_in[12];
    const float* Wv_v_b = (const float*)d_in[13];
    const float* ffn1_w = (const float*)d_in[14];
    const float* ffn1_b = (const float*)d_in[15];
    const float* ffn2_w = (const float*)d_in[16];
    const float* ffn2_b = (const float*)d_in[17];

    float* out_vt = (float*)d_out;
    float* out_tv = out_vt + ELEM1;
    float* maskO  = out_vt + 2 * ELEM1;

    static float* scr = nullptr;
    if (!scr) cudaGetSymbolAddress((void**)&scr, g_scr);
    static bool attr_done = false;
    if (!attr_done) {
        cudaFuncSetAttribute(gemm_tf32<true,  true>,  cudaFuncAttributeMaxDynamicSharedMemorySize, GEMM_SMEM);
        cudaFuncSetAttribute(gemm_tf32<true,  false>, cudaFuncAttributeMaxDynamicSharedMemorySize, GEMM_SMEM);
        cudaFuncSetAttribute(gemm_tf32<false, false>, cudaFuncAttributeMaxDynamicSharedMemorySize, GEMM_SMEM);
        attr_done = true;
    }

    float* Qv    = scr + 0 * ELEM1;
    float* Kv    = scr + 1 * ELEM1;
    float* Vv    = scr + 2 * ELEM1;
    float* Qt    = scr + 3 * ELEM1;
    float* Kt    = scr + 4 * ELEM1;
    float* Vt    = scr + 5 * ELEM1;
    float* Ssc   = scr + 6 * ELEM1;
    float* maskT = scr + 7 * ELEM1;
    float* poolV = scr + 8 * ELEM1;
    float* poolT = poolV + BATCH * DT;
    float* lv    = poolT + BATCH * DT;

    const long S1 = (long)SEQ * SEQ;

    // 1) pools + gate
    pool_kernel<<<dim3(4, BATCH), 256>>>(oV, poolV);
    pool_kernel<<<dim3(4, BATCH), 256>>>(oT, poolT);
    ffn_kernel<<<BATCH, HID>>>(poolV, poolT, ffn1_w, ffn1_b, ffn2_w, ffn2_b, lv);

    // 2) projections
    dim3 gp(8, 128, 1);
    gemm_tf32<true, true><<<gp, 256, GEMM_SMEM>>>(oV, Wq_v_w, Wq_v_b, Qv, BATCH * SEQ, DT, DT, 0, 0, 0);
    gemm_tf32<true, true><<<gp, 256, GEMM_SMEM>>>(oT, Wk_t_w, Wk_t_b, Kt, BATCH * SEQ, DT, DT, 0, 0, 0);
    gemm_tf32<true, true><<<gp, 256, GEMM_SMEM>>>(oT, Wv_t_w, Wv_t_b, Vt, BATCH * SEQ, DT, DT, 0, 0, 0);
    gemm_tf32<true, true><<<gp, 256, GEMM_SMEM>>>(oT, Wq_t_w, Wq_t_b, Qt, BATCH * SEQ, DT, DT, 0, 0, 0);
    gemm_tf32<true, true><<<gp, 256, GEMM_SMEM>>>(oV, Wk_v_w, Wk_v_b, Kv, BATCH * SEQ, DT, DT, 0, 0, 0);
    gemm_tf32<true, true><<<gp, 256, GEMM_SMEM>>>(oV, Wv_v_w, Wv_v_b, Vv, BATCH * SEQ, DT, DT, 0, 0, 0);

    dim3 gb(8, 8, BATCH);

    // 3) sim -> mask -> maskT
    gemm_tf32<true, false><<<gb, 256, GEMM_SMEM>>>(oV, oT, nullptr, Ssc, SEQ, SEQ, DT, S1, S1, S1);
    mask_kernel<<<dim3(SEQ, BATCH), 256>>>(Ssc, lv, maskO);
    transpose_kernel<<<dim3(32, 32, BATCH), dim3(32, 32)>>>(maskO, maskT);

    // 4) V->T attention
    gemm_tf32<true, false><<<gb, 256, GEMM_SMEM>>>(Qv, Kt, nullptr, Ssc, SEQ, SEQ, DT, S1, S1, S1);
    msoftmax_kernel<<<dim3(SEQ, BATCH), 256>>>(Ssc, maskO);
    gemm_tf32<false, false><<<gb, 256, GEMM_SMEM>>>(Ssc, Vt, nullptr, out_vt, SEQ, DT, SEQ, S1, S1, S1);

    // 5) T->V attention
    gemm_tf32<true, false><<<gb, 256, GEMM_SMEM>>>(Qt, Kv, nullptr, Ssc, SEQ, SEQ, DT, S1, S1, S1);
    msoftmax_kernel<<<dim3(SEQ, BATCH), 256>>>(Ssc, maskT);
    gemm_tf32<false, false><<<gb, 256, GEMM_SMEM>>>(Ssc, Vv, nullptr, out_tv, SEQ, DT, SEQ, S1, S1, S1);
}

// round 5
// speedup vs baseline: 2.4974x; 2.3073x over previous
#include <cuda_runtime.h>
#include <cuda.h>
#include <cstdint>

// ===========================================================================
#define BATCH 16
#define SEQ   1024
#define DT    1024
#define HID   512
#define NEG_INF_F (-1.0e9f)
static __device__ __host__ constexpr float INV_SQRT = 0.03125f;

static constexpr long ELEM1 = 16LL * 1024 * 1024;
__device__ __align__(1024) float g_scr[ELEM1 * 8 + 2 * BATCH * DT + 64];

// ===========================================================================
// PTX helpers
// ===========================================================================
__device__ __forceinline__ uint32_t smem_u32(const void* p) {
    uint32_t a;
    asm("{ .reg .u64 t; cvta.to.shared.u64 t, %1; cvt.u32.u64 %0, t; }" : "=r"(a) : "l"(p));
    return a;
}
__device__ __forceinline__ float lds_f(uint32_t a) {
    float v;
    asm volatile("ld.shared.f32 %0, [%1];" : "=f"(v) : "r"(a));
    return v;
}
__device__ __forceinline__ uint32_t f2tf(float f) {
    uint32_t r;
    asm volatile("cvt.rna.tf32.f32 %0, %1;" : "=r"(r) : "f"(f));
    return r;
}

#define MBARRIER_INIT(mbar, count) \
    asm volatile("mbarrier.init.shared.b64 [%0], %1;" :: "r"((uint32_t)(mbar)), "r"((uint32_t)(count)) : "memory")
#define MBARRIER_EXPECT_TX(mbar, bytes) \
    asm volatile("mbarrier.arrive.expect_tx.shared.b64 _, [%0], %1;" \
        :: "r"((uint32_t)(mbar)), "r"((uint32_t)(bytes)) : "memory")
#define MBARRIER_WAIT_PARITY(mbar, parity) do {                                  \
    uint32_t _m = (uint32_t)(mbar);  uint32_t _p = (uint32_t)(parity);           \
    asm volatile(                                                                 \
        "{\n\t.reg .pred P1;\n\t"                                                 \
        "WL_%=:\n\t"                                                              \
        "mbarrier.try_wait.parity.acquire.cta.shared::cta.b64 P1, [%0], %1, 0x989680;\n\t" \
        "@P1 bra.uni WD_%=;\n\t"                                                  \
        "bra.uni WL_%=;\n\t"                                                      \
        "WD_%=:\n\t}"                                                             \
        :: "r"(_m), "r"(_p) : "memory");                                          \
} while (0)
#define TMA_LOAD_3D(saddr, tmap, cx, cy, cz, mbar) \
    asm volatile( \
        "cp.async.bulk.tensor.3d.shared::cta.global.tile.mbarrier::complete_tx::bytes " \
        "[%0], [%1, {%2, %3, %4}], [%5];" \
        :: "r"((uint32_t)(saddr)), "l"(tmap), "r"((int)(cx)), "r"((int)(cy)), "r"((int)(cz)), \
           "r"((uint32_t)(mbar)) : "memory")

// ===========================================================================
// TMA + mma.m16n8k8.tf32 GEMM:  C[M,N] = A[M,K] @ B[N,K]^T (+bias)
// CTA tile 128x128, KT=32 per stage, 3 stages, 256 threads (8 warps).
// TRANSOUT: write C transposed per batch of 1024 rows: CT[b][n][m]
// ===========================================================================
static constexpr int BM = 128, BN = 128, KT = 32, STAGES = 3;
static constexpr int ABYT = BM * KT * 4;          // 16384
static constexpr int BBYT = BN * KT * 4;          // 16384
static constexpr int STB  = ABYT + BBYT;          // 32768
static constexpr int SMEM_DYN = 1024 + STAGES * STB;  // 99328

template <bool BIAS, bool TRANSOUT>
__global__ void __launch_bounds__(256, 2)
gemm_tc(const __grid_constant__ CUtensorMap tmA,
        const __grid_constant__ CUtensorMap tmB,
        float* __restrict__ C, const float* __restrict__ bias, long sCz)
{
    extern __shared__ char dynraw[];
    __shared__ __align__(8) unsigned long long mb[STAGES];

    uint32_t d0 = smem_u32(dynraw);
    uint32_t sb = (d0 + 1023u) & ~1023u;        // 1024-aligned SMEM base

    const int tid  = threadIdx.x;
    const int warp = tid >> 5, lane = tid & 31;
    const int wm = warp & 3, wn = warp >> 2;
    const int gID = lane >> 2, tig = lane & 3;
    const int m0 = blockIdx.y * BM, n0 = blockIdx.x * BN, z = blockIdx.z;
    const uint32_t mbase = smem_u32(mb);

    if (tid == 0) {
        for (int s = 0; s < STAGES; s++) MBARRIER_INIT(mbase + 8 * s, 1);
    }
    __syncthreads();

    if (tid == 0) {
        for (int s = 0; s < 2; s++) {
            MBARRIER_EXPECT_TX(mbase + 8 * s, STB);
            TMA_LOAD_3D(sb + s * STB,        &tmA, s * KT, m0, z, mbase + 8 * s);
            TMA_LOAD_3D(sb + s * STB + ABYT, &tmB, s * KT, n0, z, mbase + 8 * s);
        }
    }

    float acc[2][8][4];
#pragma unroll
    for (int mi = 0; mi < 2; mi++)
#pragma unroll
        for (int ni = 0; ni < 8; ni++)
#pragma unroll
            for (int e = 0; e < 4; e++) acc[mi][ni][e] = 0.0f;

    const uint32_t gx   = (uint32_t)gID << 4;            // SW128 XOR term (row&7)<<4
    const uint32_t rowA = (uint32_t)(wm * 32 + gID) * 128;
    const uint32_t rowB = (uint32_t)(wn * 64 + gID) * 128;
    const int NKT = 32;   // K = 1024

    for (int kt = 0; kt < NKT; kt++) {
        const int s = kt % 3;
        const uint32_t stg = sb + s * STB;
        MBARRIER_WAIT_PARITY(mbase + 8 * s, (kt / 3) & 1);

        if (tid == 0 && kt + 2 < NKT) {
            const int s2 = (kt + 2) % 3;
            MBARRIER_EXPECT_TX(mbase + 8 * s2, STB);
            TMA_LOAD_3D(sb + s2 * STB,        &tmA, (kt + 2) * KT, m0, z, mbase + 8 * s2);
            TMA_LOAD_3D(sb + s2 * STB + ABYT, &tmB, (kt + 2) * KT, n0, z, mbase + 8 * s2);
        }

        const uint32_t aBase = stg + rowA;
        const uint32_t bBase = stg + ABYT + rowB;

#pragma unroll
        for (int kk = 0; kk < 4; kk++) {
            // k8-step kk -> byte offset kk*8*4 = kk*32 within the 128B row
            const uint32_t off0 = ((uint32_t)(kk * 32 + tig * 4)) ^ gx;
            const uint32_t off1 = off0 ^ 16u;

            uint32_t ua[2][4], ub[8][2];
#pragma unroll
            for (int mi = 0; mi < 2; mi++) {
                ua[mi][0] = f2tf(lds_f(aBase + mi * 2048 + off0));
                ua[mi][1] = f2tf(lds_f(aBase + mi * 2048 + 1024 + off0));
                ua[mi][2] = f2tf(lds_f(aBase + mi * 2048 + off1));
                ua[mi][3] = f2tf(lds_f(aBase + mi * 2048 + 1024 + off1));
            }
#pragma unroll
            for (int ni = 0; ni < 8; ni++) {
                ub[ni][0] = f2tf(lds_f(bBase + ni * 1024 + off0));
                ub[ni][1] = f2tf(lds_f(bBase + ni * 1024 + off1));
            }
#pragma unroll
            for (int mi = 0; mi < 2; mi++)
#pragma unroll
                for (int ni = 0; ni < 8; ni++)
                    asm volatile(
                        "mma.sync.aligned.m16n8k8.row.col.f32.tf32.tf32.f32 "
                        "{%0,%1,%2,%3},{%4,%5,%6,%7},{%8,%9},{%0,%1,%2,%3};"
                        : "+f"(acc[mi][ni][0]), "+f"(acc[mi][ni][1]),
                          "+f"(acc[mi][ni][2]), "+f"(acc[mi][ni][3])
                        : "r"(ua[mi][0]), "r"(ua[mi][1]), "r"(ua[mi][2]), "r"(ua[mi][3]),
                          "r"(ub[ni][0]), "r"(ub[ni][1]));
        }
        __syncthreads();
    }

    // ---- epilogue (reuse stage SMEM as staging tile) ----
    float* ep = (float*)(dynraw + (sb - d0));
    if (BIAS) {
#pragma unroll
        for (int ni = 0; ni < 8; ni++) {
            const int nc = n0 + wn * 64 + ni * 8 + 2 * tig;
            const float b0 = __ldg(bias + nc), b1 = __ldg(bias + nc + 1);
#pragma unroll
            for (int mi = 0; mi < 2; mi++) {
                acc[mi][ni][0] += b0; acc[mi][ni][1] += b1;
                acc[mi][ni][2] += b0; acc[mi][ni][3] += b1;
            }
        }
    }

    if (!TRANSOUT) {
        const int P = 132;
#pragma unroll
        for (int mi = 0; mi < 2; mi++)
#pragma unroll
            for (int ni = 0; ni < 8; ni++) {
                const int r = wm * 32 + mi * 16 + gID;
                const int c = wn * 64 + ni * 8 + 2 * tig;
                *(float2*)(ep + r * P + c)       = make_float2(acc[mi][ni][0], acc[mi][ni][1]);
                *(float2*)(ep + (r + 8) * P + c) = make_float2(acc[mi][ni][2], acc[mi][ni][3]);
            }
        __syncthreads();
        float* Cz = C + (long)z * sCz;
#pragma unroll
        for (int it = 0; it < 16; it++) {
            const int idx = tid + it * 256;
            const int r = idx >> 5, c4 = (idx & 31) * 4;
            float4 v = *(float4*)(ep + r * P + c4);
            *(float4*)(Cz + (long)(m0 + r) * 1024 + n0 + c4) = v;
        }
    } else {
        const int P = 129;
#pragma unroll
        for (int mi = 0; mi < 2; mi++)
#pragma unroll
            for (int ni = 0; ni < 8; ni++) {
                const int r = wm * 32 + mi * 16 + gID;
                const int c = wn * 64 + ni * 8 + 2 * tig;
                ep[r * P + c]           = acc[mi][ni][0];
                ep[r * P + c + 1]       = acc[mi][ni][1];
                ep[(r + 8) * P + c]     = acc[mi][ni][2];
                ep[(r + 8) * P + c + 1] = acc[mi][ni][3];
            }
        __syncthreads();
        const int b  = m0 >> 10;
        const int mlb = m0 & 1023;
#pragma unroll
        for (int it = 0; it < 64; it++) {
            const int idx = tid + it * 256;
            const int n = idx >> 7, m = idx & 127;
            C[((long)b << 20) + (long)(n0 + n) * 1024 + (mlb + m)] = ep[m * P + n];
        }
    }
}

// ===========================================================================
// Elementwise kernels (unchanged, known correct)
// ===========================================================================
__global__ void pool_kernel(const float* __restrict__ src, float* __restrict__ dst)
{
    int b = blockIdx.y;
    int d = blockIdx.x * 256 + threadIdx.x;
    const float* p = src + ((long)b << 20) + d;
    float s = 0.f;
#pragma unroll 8
    for (int m = 0; m < SEQ; m++) s += p[(long)m << 10];
    dst[b * DT + d] = s * (1.0f / 1024.0f);
}

__global__ void ffn_kernel(const float* __restrict__ poolV, const float* __restrict__ poolT,
                           const float* __restrict__ w1, const float* __restrict__ b1,
                           const float* __restrict__ w2, const float* __restrict__ b2,
                           float* __restrict__ lout)
{
    __shared__ float x[2 * DT];
    __shared__ float red[HID];
    int b = blockIdx.x, t = threadIdx.x;
    for (int i = t; i < 2 * DT; i += HID)
        x[i] = (i < DT) ? poolV[b * DT + i] : poolT[b * DT + (i - DT)];
    __syncthreads();
    float acc = b1[t];
    const float* wr = w1 + (long)t * (2 * DT);
#pragma unroll 8
    for (int k = 0; k < 2 * DT; k++) acc += wr[k] * x[k];
    float h = fmaxf(acc, 0.0f);
    red[t] = h * w2[t];
    __syncthreads();
    for (int s = HID / 2; s > 0; s >>= 1) {
        if (t < s) red[t] += red[t + s];
        __syncthreads();
    }
    if (t == 0) lout[b] = 1.0f / (1.0f + expf(-(red[0] + b2[0])));
}

__device__ __forceinline__ float block_max(float v, float* red)
{
    int t = threadIdx.x;
    red[t] = v; __syncthreads();
    for (int s = 128; s > 0; s >>= 1) {
        if (t < s) red[t] = fmaxf(red[t], red[t + s]);
        __syncthreads();
    }
    float r = red[0]; __syncthreads();
    return r;
}
__device__ __forceinline__ float block_sum(float v, float* red)
{
    int t = threadIdx.x;
    red[t] = v; __syncthreads();
    for (int s = 128; s > 0; s >>= 1) {
        if (t < s) red[t] += red[t + s];
        __syncthreads();
    }
    float r = red[0]; __syncthreads();
    return r;
}

__global__ void mask_kernel(const float* __restrict__ S, const float* __restrict__ lv,
                            float* __restrict__ maskO)
{
    __shared__ float red[256];
    int t = threadIdx.x;
    long row = (long)blockIdx.y * SEQ + blockIdx.x;
    const float* p = S + row * SEQ;
    float x[4];
    float mx = -3.4e38f;
#pragma unroll
    for (int i = 0; i < 4; i++) {
        x[i] = p[t + i * 256] * INV_SQRT;
        mx = fmaxf(mx, x[i]);
    }
    mx = block_max(mx, red);
    float s = 0.f;
#pragma unroll
    for (int i = 0; i < 4; i++) s += expf(x[i] - mx);
    s = block_sum(s, red);
    float l = lv[blockIdx.y];
    float* o = maskO + row * SEQ;
#pragma unroll
    for (int i = 0; i < 4; i++)
        o[t + i * 256] = ((expf(x[i] - mx) / s) >= l) ? 1.0f : 0.0f;
}

__global__ void msoftmax_kernel(float* __restrict__ S, const float* __restrict__ maskM)
{
    __shared__ float red[256];
    int t = threadIdx.x;
    long row = (long)blockIdx.y * SEQ + blockIdx.x;
    float* p = S + row * SEQ;
    const float* mk = maskM + row * SEQ;
    float x[4];
    float mx = -3.4e38f;
#pragma unroll
    for (int i = 0; i < 4; i++) {
        int idx = t + i * 256;
        x[i] = (mk[idx] != 0.0f) ? p[idx] * INV_SQRT : NEG_INF_F;
        mx = fmaxf(mx, x[i]);
    }
    mx = block_max(mx, red);
    float s = 0.f;
#pragma unroll
    for (int i = 0; i < 4; i++) s += expf(x[i] - mx);
    s = block_sum(s, red);
#pragma unroll
    for (int i = 0; i < 4; i++)
        p[t + i * 256] = expf(x[i] - mx) / s;
}

__global__ void transpose_kernel(const float* __restrict__ in, float* __restrict__ out)
{
    __shared__ float tile[32][33];
    long base = (long)blockIdx.z << 20;
    int m = blockIdx.y * 32 + threadIdx.y;
    int n = blockIdx.x * 32 + threadIdx.x;
    tile[threadIdx.y][threadIdx.x] = in[base + (long)m * SEQ + n];
    __syncthreads();
    int n2 = blockIdx.x * 32 + threadIdx.y;
    int m2 = blockIdx.y * 32 + threadIdx.x;
    out[base + (long)n2 * SEQ + m2] = tile[threadIdx.x][threadIdx.y];
}

// ===========================================================================
// Host side
// ===========================================================================
typedef CUresult (*PFN_encodeTiled)(CUtensorMap*, CUtensorMapDataType, cuuint32_t, void*,
                                    const cuuint64_t*, const cuuint64_t*, const cuuint32_t*,
                                    const cuuint32_t*, CUtensorMapInterleave, CUtensorMapSwizzle,
                                    CUtensorMapL2promotion, CUtensorMapFloatOOBfill);
static PFN_encodeTiled g_enc = nullptr;

static void enc3d(CUtensorMap* tm, const void* p, long K, long R, long Z)
{
    cuuint64_t dims[3] = {(cuuint64_t)K, (cuuint64_t)R, (cuuint64_t)Z};
    cuuint64_t str[2]  = {(cuuint64_t)(K * 4), (cuuint64_t)(K * R * 4)};
    cuuint32_t box[3]  = {(cuuint32_t)KT, 128, 1};
    cuuint32_t es[3]   = {1, 1, 1};
    g_enc(tm, CU_TENSOR_MAP_DATA_TYPE_FLOAT32, 3, (void*)p, dims, str, box, es,
          CU_TENSOR_MAP_INTERLEAVE_NONE, CU_TENSOR_MAP_SWIZZLE_128B,
          CU_TENSOR_MAP_L2_PROMOTION_L2_128B, CU_TENSOR_MAP_FLOAT_OOB_FILL_NONE);
}

extern "C" void kernel_launch(void* const* d_in, const int* in_sizes, int n_in,
                              void* d_out, int out_size)
{
    (void)in_sizes; (void)n_in; (void)out_size;

    const float* oV     = (const float*)d_in[0];
    const float* oT     = (const float*)d_in[1];
    const float* Wq_v_w = (const float*)d_in[2];
    const float* Wq_v_b = (const float*)d_in[3];
    const float* Wk_t_w = (const float*)d_in[4];
    const float* Wk_t_b = (const float*)d_in[5];
    const float* Wv_t_w = (const float*)d_in[6];
    const float* Wv_t_b = (const float*)d_in[7];
    const float* Wq_t_w = (const float*)d_in[8];
    const float* Wq_t_b = (const float*)d_in[9];
    const float* Wk_v_w = (const float*)d_in[10];
    const float* Wk_v_b = (const float*)d_in[11];
    const float* Wv_v_w = (const float*)d_in[12];
    const float* Wv_v_b = (const float*)d_in[13];
    const float* ffn1_w = (const float*)d_in[14];
    const float* ffn1_b = (const float*)d_in[15];
    const float* ffn2_w = (const float*)d_in[16];
    const float* ffn2_b = (const float*)d_in[17];

    float* out_vt = (float*)d_out;
    float* out_tv = out_vt + ELEM1;
    float* maskO  = out_vt + 2 * ELEM1;

    static float* scr = nullptr;
    if (!scr) cudaGetSymbolAddress((void**)&scr, g_scr);
    if (!g_enc) {
        void* p = nullptr;
        cudaDriverEntryPointQueryResult st;
        cudaGetDriverEntryPoint("cuTensorMapEncodeTiled", &p, cudaEnableDefault, &st);
        g_enc = (PFN_encodeTiled)p;
    }
    static bool attr_done = false;
    if (!attr_done) {
        cudaFuncSetAttribute(gemm_tc<true,  false>, cudaFuncAttributeMaxDynamicSharedMemorySize, SMEM_DYN);
        cudaFuncSetAttribute(gemm_tc<true,  true>,  cudaFuncAttributeMaxDynamicSharedMemorySize, SMEM_DYN);
        cudaFuncSetAttribute(gemm_tc<false, false>, cudaFuncAttributeMaxDynamicSharedMemorySize, SMEM_DYN);
        attr_done = true;
    }

    float* Qv    = scr + 0 * ELEM1;
    float* Kt    = scr + 1 * ELEM1;
    float* VtT   = scr + 2 * ELEM1;   // (B, DT, SEQ)
    float* Qt    = scr + 3 * ELEM1;
    float* Kv    = scr + 4 * ELEM1;
    float* VvT   = scr + 5 * ELEM1;   // (B, DT, SEQ)
    float* Ssc   = scr + 6 * ELEM1;
    float* maskT = scr + 7 * ELEM1;
    float* poolV = scr + 8 * ELEM1;
    float* poolT = poolV + BATCH * DT;
    float* lv    = poolT + BATCH * DT;

    // 1) pools + gate
    pool_kernel<<<dim3(4, BATCH), 256>>>(oV, poolV);
    pool_kernel<<<dim3(4, BATCH), 256>>>(oT, poolT);
    ffn_kernel<<<BATCH, HID>>>(poolV, poolT, ffn1_w, ffn1_b, ffn2_w, ffn2_b, lv);

    CUtensorMap tA, tB;
    const dim3 gp(8, 128, 1);     // projections
    const dim3 gb(8, 8, BATCH);   // batched per-z

    // 2) projections
    enc3d(&tA, oV, DT, BATCH * SEQ, 1);
    enc3d(&tB, Wq_v_w, DT, DT, 1);
    gemm_tc<true, false><<<gp, 256, SMEM_DYN>>>(tA, tB, Qv, Wq_v_b, 0);
    enc3d(&tB, Wk_v_w, DT, DT, 1);
    gemm_tc<true, false><<<gp, 256, SMEM_DYN>>>(tA, tB, Kv, Wk_v_b, 0);
    enc3d(&tB, Wv_v_w, DT, DT, 1);
    gemm_tc<true, true ><<<gp, 256, SMEM_DYN>>>(tA, tB, VvT, Wv_v_b, 0);

    enc3d(&tA, oT, DT, BATCH * SEQ, 1);
    enc3d(&tB, Wk_t_w, DT, DT, 1);
    gemm_tc<true, false><<<gp, 256, SMEM_DYN>>>(tA, tB, Kt, Wk_t_b, 0);
    enc3d(&tB, Wv_t_w, DT, DT, 1);
    gemm_tc<true, true ><<<gp, 256, SMEM_DYN>>>(tA, tB, VtT, Wv_t_b, 0);
    enc3d(&tB, Wq_t_w, DT, DT, 1);
    gemm_tc<true, false><<<gp, 256, SMEM_DYN>>>(tA, tB, Qt, Wq_t_b, 0);

    const long S1 = (long)SEQ * SEQ;

    // 3) sim -> mask -> maskT
    enc3d(&tA, oV, DT, SEQ, BATCH);
    enc3d(&tB, oT, DT, SEQ, BATCH);
    gemm_tc<false, false><<<gb, 256, SMEM_DYN>>>(tA, tB, Ssc, nullptr, S1);
    mask_kernel<<<dim3(SEQ, BATCH), 256>>>(Ssc, lv, maskO);
    transpose_kernel<<<dim3(32, 32, BATCH), dim3(32, 32)>>>(maskO, maskT);

    // 4) V->T attention
    enc3d(&tA, Qv, DT, SEQ, BATCH);
    enc3d(&tB, Kt, DT, SEQ, BATCH);
    gemm_tc<false, false><<<gb, 256, SMEM_DYN>>>(tA, tB, Ssc, nullptr, S1);
    msoftmax_kernel<<<dim3(SEQ, BATCH), 256>>>(Ssc, maskO);
    enc3d(&tA, Ssc, SEQ, SEQ, BATCH);
    enc3d(&tB, VtT, SEQ, DT, BATCH);
    gemm_tc<false, false><<<gb, 256, SMEM_DYN>>>(tA, tB, out_vt, nullptr, S1);

    // 5) T->V attention
    enc3d(&tA, Qt, DT, SEQ, BATCH);
    enc3d(&tB, Kv, DT, SEQ, BATCH);
    gemm_tc<false, false><<<gb, 256, SMEM_DYN>>>(tA, tB, Ssc, nullptr, S1);
    msoftmax_kernel<<<dim3(SEQ, BATCH), 256>>>(Ssc, maskT);
    enc3d(&tA, Ssc, SEQ, SEQ, BATCH);
    enc3d(&tB, VvT, SEQ, DT, BATCH);
    gemm_tc<false, false><<<gb, 256, SMEM_DYN>>>(tA, tB, out_tv, nullptr, S1);
}

// round 6
// speedup vs baseline: 2.6174x; 1.0481x over previous
#include <cuda_runtime.h>
#include <cuda.h>
#include <cstdint>

// ===========================================================================
#define BATCH 16
#define SEQ   1024
#define DT    1024
#define HID   512
#define NEG_INF_F (-1.0e9f)
static __device__ __host__ constexpr float INV_SQRT = 0.03125f;

static constexpr long ELEM1 = 16LL * 1024 * 1024;
// 10 big tensors + 6 rounded weights + pools/gate
__device__ __align__(1024) float g_scr[ELEM1 * 10 + 6L * DT * DT + 2 * BATCH * DT + 64];

// ===========================================================================
// PTX helpers
// ===========================================================================
__device__ __forceinline__ uint32_t smem_u32(const void* p) {
    uint32_t a;
    asm("{ .reg .u64 t; cvta.to.shared.u64 t, %1; cvt.u32.u64 %0, t; }" : "=r"(a) : "l"(p));
    return a;
}
__device__ __forceinline__ uint32_t lds_u(uint32_t a) {
    uint32_t v;
    asm volatile("ld.shared.b32 %0, [%1];" : "=r"(v) : "r"(a));
    return v;
}
__device__ __forceinline__ float rnd_tf32(float f) {
    uint32_t r;
    asm volatile("cvt.rna.tf32.f32 %0, %1;" : "=r"(r) : "f"(f));
    return __uint_as_float(r);
}

#define MBARRIER_INIT(mbar, count) \
    asm volatile("mbarrier.init.shared.b64 [%0], %1;" :: "r"((uint32_t)(mbar)), "r"((uint32_t)(count)) : "memory")
#define MBARRIER_EXPECT_TX(mbar, bytes) \
    asm volatile("mbarrier.arrive.expect_tx.shared.b64 _, [%0], %1;" \
        :: "r"((uint32_t)(mbar)), "r"((uint32_t)(bytes)) : "memory")
#define MBARRIER_WAIT_PARITY(mbar, parity) do {                                  \
    uint32_t _m = (uint32_t)(mbar);  uint32_t _p = (uint32_t)(parity);           \
    asm volatile(                                                                 \
        "{\n\t.reg .pred P1;\n\t"                                                 \
        "WL_%=:\n\t"                                                              \
        "mbarrier.try_wait.parity.acquire.cta.shared::cta.b64 P1, [%0], %1, 0x989680;\n\t" \
        "@P1 bra.uni WD_%=;\n\t"                                                  \
        "bra.uni WL_%=;\n\t"                                                      \
        "WD_%=:\n\t}"                                                             \
        :: "r"(_m), "r"(_p) : "memory");                                          \
} while (0)
#define TMA_LOAD_3D(saddr, tmap, cx, cy, cz, mbar) \
    asm volatile( \
        "cp.async.bulk.tensor.3d.shared::cta.global.tile.mbarrier::complete_tx::bytes " \
        "[%0], [%1, {%2, %3, %4}], [%5];" \
        :: "r"((uint32_t)(saddr)), "l"(tmap), "r"((int)(cx)), "r"((int)(cy)), "r"((int)(cz)), \
           "r"((uint32_t)(mbar)) : "memory")

// ===========================================================================
// TMA + mma.m16n8k8.tf32 GEMM:  C[M,N] = A[M,K] @ B[N,K]^T (+bias)
// CTA tile 128x128, KT=32 per stage, 3 stages, 256 threads.
// Inputs must already be tf32-rounded (HW truncation is then exact).
// BIAS also implies rounding the output to tf32 (projection outputs feed GEMMs).
// TRANSOUT: write C transposed per batch of 1024 rows: CT[b][n][m]
// ===========================================================================
static constexpr int BM = 128, BN = 128, KT = 32, STAGES = 3;
static constexpr int ABYT = BM * KT * 4;
static constexpr int BBYT = BN * KT * 4;
static constexpr int STB  = ABYT + BBYT;          // 32768
static constexpr int SMEM_DYN = 1024 + STAGES * STB;  // 99328

template <bool BIAS, bool TRANSOUT>
__global__ void __launch_bounds__(256, 2)
gemm_tc(const __grid_constant__ CUtensorMap tmA,
        const __grid_constant__ CUtensorMap tmB,
        float* __restrict__ C, const float* __restrict__ bias, long sCz)
{
    extern __shared__ char dynraw[];
    __shared__ __align__(8) unsigned long long mb[STAGES];

    uint32_t d0 = smem_u32(dynraw);
    uint32_t sb = (d0 + 1023u) & ~1023u;

    const int tid  = threadIdx.x;
    const int warp = tid >> 5, lane = tid & 31;
    const int wm = warp & 3, wn = warp >> 2;
    const int gID = lane >> 2, tig = lane & 3;
    const int m0 = blockIdx.y * BM, n0 = blockIdx.x * BN, z = blockIdx.z;
    const uint32_t mbase = smem_u32(mb);

    if (tid == 0) {
        for (int s = 0; s < STAGES; s++) MBARRIER_INIT(mbase + 8 * s, 1);
    }
    __syncthreads();

    if (tid == 0) {
        for (int s = 0; s < 2; s++) {
            MBARRIER_EXPECT_TX(mbase + 8 * s, STB);
            TMA_LOAD_3D(sb + s * STB,        &tmA, s * KT, m0, z, mbase + 8 * s);
            TMA_LOAD_3D(sb + s * STB + ABYT, &tmB, s * KT, n0, z, mbase + 8 * s);
        }
    }

    float acc[2][8][4];
#pragma unroll
    for (int mi = 0; mi < 2; mi++)
#pragma unroll
        for (int ni = 0; ni < 8; ni++)
#pragma unroll
            for (int e = 0; e < 4; e++) acc[mi][ni][e] = 0.0f;

    const uint32_t gx   = (uint32_t)gID << 4;            // SW128 XOR term
    const uint32_t rowA = (uint32_t)(wm * 32 + gID) * 128;
    const uint32_t rowB = (uint32_t)(wn * 64 + gID) * 128;
    const int NKT = 32;   // K = 1024

    for (int kt = 0; kt < NKT; kt++) {
        const int s = kt % 3;
        const uint32_t stg = sb + s * STB;
        MBARRIER_WAIT_PARITY(mbase + 8 * s, (kt / 3) & 1);

        if (tid == 0 && kt + 2 < NKT) {
            const int s2 = (kt + 2) % 3;
            MBARRIER_EXPECT_TX(mbase + 8 * s2, STB);
            TMA_LOAD_3D(sb + s2 * STB,        &tmA, (kt + 2) * KT, m0, z, mbase + 8 * s2);
            TMA_LOAD_3D(sb + s2 * STB + ABYT, &tmB, (kt + 2) * KT, n0, z, mbase + 8 * s2);
        }

        const uint32_t aBase = stg + rowA;
        const uint32_t bBase = stg + ABYT + rowB;

#pragma unroll
        for (int kk = 0; kk < 4; kk++) {
            const uint32_t off0 = ((uint32_t)(kk * 32 + tig * 4)) ^ gx;
            const uint32_t off1 = off0 ^ 16u;

            uint32_t ua[2][4], ub[8][2];
#pragma unroll
            for (int mi = 0; mi < 2; mi++) {
                ua[mi][0] = lds_u(aBase + mi * 2048 + off0);
                ua[mi][1] = lds_u(aBase + mi * 2048 + 1024 + off0);
                ua[mi][2] = lds_u(aBase + mi * 2048 + off1);
                ua[mi][3] = lds_u(aBase + mi * 2048 + 1024 + off1);
            }
#pragma unroll
            for (int ni = 0; ni < 8; ni++) {
                ub[ni][0] = lds_u(bBase + ni * 1024 + off0);
                ub[ni][1] = lds_u(bBase + ni * 1024 + off1);
            }
#pragma unroll
            for (int mi = 0; mi < 2; mi++)
#pragma unroll
                for (int ni = 0; ni < 8; ni++)
                    asm volatile(
                        "mma.sync.aligned.m16n8k8.row.col.f32.tf32.tf32.f32 "
                        "{%0,%1,%2,%3},{%4,%5,%6,%7},{%8,%9},{%0,%1,%2,%3};"
                        : "+f"(acc[mi][ni][0]), "+f"(acc[mi][ni][1]),
                          "+f"(acc[mi][ni][2]), "+f"(acc[mi][ni][3])
                        : "r"(ua[mi][0]), "r"(ua[mi][1]), "r"(ua[mi][2]), "r"(ua[mi][3]),
                          "r"(ub[ni][0]), "r"(ub[ni][1]));
        }
        __syncthreads();
    }

    // ---- epilogue (reuse stage SMEM as staging tile) ----
    float* ep = (float*)(dynraw + (sb - d0));
    if (BIAS) {
#pragma unroll
        for (int ni = 0; ni < 8; ni++) {
            const int nc = n0 + wn * 64 + ni * 8 + 2 * tig;
            const float b0 = __ldg(bias + nc), b1 = __ldg(bias + nc + 1);
#pragma unroll
            for (int mi = 0; mi < 2; mi++) {
                acc[mi][ni][0] = rnd_tf32(acc[mi][ni][0] + b0);
                acc[mi][ni][1] = rnd_tf32(acc[mi][ni][1] + b1);
                acc[mi][ni][2] = rnd_tf32(acc[mi][ni][2] + b0);
                acc[mi][ni][3] = rnd_tf32(acc[mi][ni][3] + b1);
            }
        }
    }

    if (!TRANSOUT) {
        const int P = 132;
#pragma unroll
        for (int mi = 0; mi < 2; mi++)
#pragma unroll
            for (int ni = 0; ni < 8; ni++) {
                const int r = wm * 32 + mi * 16 + gID;
                const int c = wn * 64 + ni * 8 + 2 * tig;
                *(float2*)(ep + r * P + c)       = make_float2(acc[mi][ni][0], acc[mi][ni][1]);
                *(float2*)(ep + (r + 8) * P + c) = make_float2(acc[mi][ni][2], acc[mi][ni][3]);
            }
        __syncthreads();
        float* Cz = C + (long)z * sCz;
#pragma unroll
        for (int it = 0; it < 16; it++) {
            const int idx = tid + it * 256;
            const int r = idx >> 5, c4 = (idx & 31) * 4;
            float4 v = *(float4*)(ep + r * P + c4);
            *(float4*)(Cz + (long)(m0 + r) * 1024 + n0 + c4) = v;
        }
    } else {
        const int P = 129;
#pragma unroll
        for (int mi = 0; mi < 2; mi++)
#pragma unroll
            for (int ni = 0; ni < 8; ni++) {
                const int r = wm * 32 + mi * 16 + gID;
                const int c = wn * 64 + ni * 8 + 2 * tig;
                ep[r * P + c]           = acc[mi][ni][0];
                ep[r * P + c + 1]       = acc[mi][ni][1];
                ep[(r + 8) * P + c]     = acc[mi][ni][2];
                ep[(r + 8) * P + c + 1] = acc[mi][ni][3];
            }
        __syncthreads();
        const int b  = m0 >> 10;
        const int mlb = m0 & 1023;
#pragma unroll
        for (int it = 0; it < 64; it++) {
            const int idx = tid + it * 256;
            const int n = idx >> 7, m = idx & 127;
            C[((long)b << 20) + (long)(n0 + n) * 1024 + (mlb + m)] = ep[m * P + n];
        }
    }
}

// ===========================================================================
// Pre-round to tf32 (rna), vectorized
// ===========================================================================
__global__ void round_kernel(const float4* __restrict__ in, float4* __restrict__ out, long n4)
{
    long i = (long)blockIdx.x * blockDim.x + threadIdx.x;
    long stride = (long)gridDim.x * blockDim.x;
    for (; i < n4; i += stride) {
        float4 v = in[i];
        v.x = rnd_tf32(v.x); v.y = rnd_tf32(v.y);
        v.z = rnd_tf32(v.z); v.w = rnd_tf32(v.w);
        out[i] = v;
    }
}

// ===========================================================================
// Elementwise kernels
// ===========================================================================
__global__ void pool_kernel(const float* __restrict__ src, float* __restrict__ dst)
{
    int b = blockIdx.y;
    int d = blockIdx.x * 256 + threadIdx.x;
    const float* p = src + ((long)b << 20) + d;
    float s = 0.f;
#pragma unroll 8
    for (int m = 0; m < SEQ; m++) s += p[(long)m << 10];
    dst[b * DT + d] = s * (1.0f / 1024.0f);
}

__global__ void ffn_kernel(const float* __restrict__ poolV, const float* __restrict__ poolT,
                           const float* __restrict__ w1, const float* __restrict__ b1,
                           const float* __restrict__ w2, const float* __restrict__ b2,
                           float* __restrict__ lout)
{
    __shared__ float x[2 * DT];
    __shared__ float red[HID];
    int b = blockIdx.x, t = threadIdx.x;
    for (int i = t; i < 2 * DT; i += HID)
        x[i] = (i < DT) ? poolV[b * DT + i] : poolT[b * DT + (i - DT)];
    __syncthreads();
    float acc = b1[t];
    const float* wr = w1 + (long)t * (2 * DT);
#pragma unroll 8
    for (int k = 0; k < 2 * DT; k++) acc += wr[k] * x[k];
    float h = fmaxf(acc, 0.0f);
    red[t] = h * w2[t];
    __syncthreads();
    for (int s = HID / 2; s > 0; s >>= 1) {
        if (t < s) red[t] += red[t + s];
        __syncthreads();
    }
    if (t == 0) lout[b] = 1.0f / (1.0f + expf(-(red[0] + b2[0])));
}

__device__ __forceinline__ float block_max(float v, float* red)
{
    int t = threadIdx.x;
    red[t] = v; __syncthreads();
    for (int s = 128; s > 0; s >>= 1) {
        if (t < s) red[t] = fmaxf(red[t], red[t + s]);
        __syncthreads();
    }
    float r = red[0]; __syncthreads();
    return r;
}
__device__ __forceinline__ float block_sum(float v, float* red)
{
    int t = threadIdx.x;
    red[t] = v; __syncthreads();
    for (int s = 128; s > 0; s >>= 1) {
        if (t < s) red[t] += red[t + s];
        __syncthreads();
    }
    float r = red[0]; __syncthreads();
    return r;
}

__global__ void mask_kernel(const float* __restrict__ S, const float* __restrict__ lv,
                            float* __restrict__ maskO)
{
    __shared__ float red[256];
    int t = threadIdx.x;
    long row = (long)blockIdx.y * SEQ + blockIdx.x;
    const float* p = S + row * SEQ;
    float x[4];
    float mx = -3.4e38f;
#pragma unroll
    for (int i = 0; i < 4; i++) {
        x[i] = p[t + i * 256] * INV_SQRT;
        mx = fmaxf(mx, x[i]);
    }
    mx = block_max(mx, red);
    float s = 0.f;
#pragma unroll
    for (int i = 0; i < 4; i++) s += expf(x[i] - mx);
    s = block_sum(s, red);
    float l = lv[blockIdx.y];
    float* o = maskO + row * SEQ;
#pragma unroll
    for (int i = 0; i < 4; i++)
        o[t + i * 256] = ((expf(x[i] - mx) / s) >= l) ? 1.0f : 0.0f;
}

// masked softmax; outputs rounded to tf32 (they feed the attn@V GEMM)
__global__ void msoftmax_kernel(float* __restrict__ S, const float* __restrict__ maskM)
{
    __shared__ float red[256];
    int t = threadIdx.x;
    long row = (long)blockIdx.y * SEQ + blockIdx.x;
    float* p = S + row * SEQ;
    const float* mk = maskM + row * SEQ;
    float x[4];
    float mx = -3.4e38f;
#pragma unroll
    for (int i = 0; i < 4; i++) {
        int idx = t + i * 256;
        x[i] = (mk[idx] != 0.0f) ? p[idx] * INV_SQRT : NEG_INF_F;
        mx = fmaxf(mx, x[i]);
    }
    mx = block_max(mx, red);
    float s = 0.f;
#pragma unroll
    for (int i = 0; i < 4; i++) s += expf(x[i] - mx);
    s = block_sum(s, red);
#pragma unroll
    for (int i = 0; i < 4; i++)
        p[t + i * 256] = rnd_tf32(expf(x[i] - mx) / s);
}

__global__ void transpose_kernel(const float* __restrict__ in, float* __restrict__ out)
{
    __shared__ float tile[32][33];
    long base = (long)blockIdx.z << 20;
    int m = blockIdx.y * 32 + threadIdx.y;
    int n = blockIdx.x * 32 + threadIdx.x;
    tile[threadIdx.y][threadIdx.x] = in[base + (long)m * SEQ + n];
    __syncthreads();
    int n2 = blockIdx.x * 32 + threadIdx.y;
    int m2 = blockIdx.y * 32 + threadIdx.x;
    out[base + (long)n2 * SEQ + m2] = tile[threadIdx.x][threadIdx.y];
}

// ===========================================================================
// Host side
// ===========================================================================
typedef CUresult (*PFN_encodeTiled)(CUtensorMap*, CUtensorMapDataType, cuuint32_t, void*,
                                    const cuuint64_t*, const cuuint64_t*, const cuuint32_t*,
                                    const cuuint32_t*, CUtensorMapInterleave, CUtensorMapSwizzle,
                                    CUtensorMapL2promotion, CUtensorMapFloatOOBfill);
static PFN_encodeTiled g_enc = nullptr;

static void enc3d(CUtensorMap* tm, const void* p, long K, long R, long Z)
{
    cuuint64_t dims[3] = {(cuuint64_t)K, (cuuint64_t)R, (cuuint64_t)Z};
    cuuint64_t str[2]  = {(cuuint64_t)(K * 4), (cuuint64_t)(K * R * 4)};
    cuuint32_t box[3]  = {(cuuint32_t)KT, 128, 1};
    cuuint32_t es[3]   = {1, 1, 1};
    g_enc(tm, CU_TENSOR_MAP_DATA_TYPE_FLOAT32, 3, (void*)p, dims, str, box, es,
          CU_TENSOR_MAP_INTERLEAVE_NONE, CU_TENSOR_MAP_SWIZZLE_128B,
          CU_TENSOR_MAP_L2_PROMOTION_L2_128B, CU_TENSOR_MAP_FLOAT_OOB_FILL_NONE);
}

extern "C" void kernel_launch(void* const* d_in, const int* in_sizes, int n_in,
                              void* d_out, int out_size)
{
    (void)in_sizes; (void)n_in; (void)out_size;

    const float* oV     = (const float*)d_in[0];
    const float* oT     = (const float*)d_in[1];
    const float* Wq_v_w = (const float*)d_in[2];
    const float* Wq_v_b = (const float*)d_in[3];
    const float* Wk_t_w = (const float*)d_in[4];
    const float* Wk_t_b = (const float*)d_in[5];
    const float* Wv_t_w = (const float*)d_in[6];
    const float* Wv_t_b = (const float*)d_in[7];
    const float* Wq_t_w = (const float*)d_in[8];
    const float* Wq_t_b = (const float*)d_in[9];
    const float* Wk_v_w = (const float*)d_in[10];
    const float* Wk_v_b = (const float*)d_in[11];
    const float* Wv_v_w = (const float*)d_in[12];
    const float* Wv_v_b = (const float*)d_in[13];
    const float* ffn1_w = (const float*)d_in[14];
    const float* ffn1_b = (const float*)d_in[15];
    const float* ffn2_w = (const float*)d_in[16];
    const float* ffn2_b = (const float*)d_in[17];

    float* out_vt = (float*)d_out;
    float* out_tv = out_vt + ELEM1;
    float* maskO  = out_vt + 2 * ELEM1;

    static float* scr = nullptr;
    if (!scr) cudaGetSymbolAddress((void**)&scr, g_scr);
    if (!g_enc) {
        void* p = nullptr;
        cudaDriverEntryPointQueryResult st;
        cudaGetDriverEntryPoint("cuTensorMapEncodeTiled", &p, cudaEnableDefault, &st);
        g_enc = (PFN_encodeTiled)p;
    }
    static bool attr_done = false;
    if (!attr_done) {
        cudaFuncSetAttribute(gemm_tc<true,  false>, cudaFuncAttributeMaxDynamicSharedMemorySize, SMEM_DYN);
        cudaFuncSetAttribute(gemm_tc<true,  true>,  cudaFuncAttributeMaxDynamicSharedMemorySize, SMEM_DYN);
        cudaFuncSetAttribute(gemm_tc<false, false>, cudaFuncAttributeMaxDynamicSharedMemorySize, SMEM_DYN);
        attr_done = true;
    }

    float* Qv    = scr + 0 * ELEM1;
    float* Kt    = scr + 1 * ELEM1;
    float* VtT   = scr + 2 * ELEM1;   // (B, DT, SEQ)
    float* Qt    = scr + 3 * ELEM1;
    float* Kv    = scr + 4 * ELEM1;
    float* VvT   = scr + 5 * ELEM1;   // (B, DT, SEQ)
    float* Ssc   = scr + 6 * ELEM1;
    float* maskT = scr + 7 * ELEM1;
    float* oVr   = scr + 8 * ELEM1;   // tf32-rounded copies
    float* oTr   = scr + 9 * ELEM1;
    float* Wr    = scr + 10 * ELEM1;  // 6 rounded weights, 1M floats each
    float* poolV = Wr + 6L * DT * DT;
    float* poolT = poolV + BATCH * DT;
    float* lv    = poolT + BATCH * DT;

    // 0) pre-round GEMM inputs to tf32
    const long N4BIG = ELEM1 / 4;
    round_kernel<<<2048, 256>>>((const float4*)oV, (float4*)oVr, N4BIG);
    round_kernel<<<2048, 256>>>((const float4*)oT, (float4*)oTr, N4BIG);
    const long N4W = (long)DT * DT / 4;
    round_kernel<<<512, 256>>>((const float4*)Wq_v_w, (float4*)(Wr + 0L * DT * DT), N4W);
    round_kernel<<<512, 256>>>((const float4*)Wk_v_w, (float4*)(Wr + 1L * DT * DT), N4W);
    round_kernel<<<512, 256>>>((const float4*)Wv_v_w, (float4*)(Wr + 2L * DT * DT), N4W);
    round_kernel<<<512, 256>>>((const float4*)Wk_t_w, (float4*)(Wr + 3L * DT * DT), N4W);
    round_kernel<<<512, 256>>>((const float4*)Wv_t_w, (float4*)(Wr + 4L * DT * DT), N4W);
    round_kernel<<<512, 256>>>((const float4*)Wq_t_w, (float4*)(Wr + 5L * DT * DT), N4W);

    // 1) pools + gate (use original fp32 inputs)
    pool_kernel<<<dim3(4, BATCH), 256>>>(oV, poolV);
    pool_kernel<<<dim3(4, BATCH), 256>>>(oT, poolT);
    ffn_kernel<<<BATCH, HID>>>(poolV, poolT, ffn1_w, ffn1_b, ffn2_w, ffn2_b, lv);

    CUtensorMap tA, tB;
    const dim3 gp(8, 128, 1);
    const dim3 gb(8, 8, BATCH);

    // 2) projections (rounded inputs; outputs rounded in epilogue)
    enc3d(&tA, oVr, DT, BATCH * SEQ, 1);
    enc3d(&tB, Wr + 0L * DT * DT, DT, DT, 1);
    gemm_tc<true, false><<<gp, 256, SMEM_DYN>>>(tA, tB, Qv, Wq_v_b, 0);
    enc3d(&tB, Wr + 1L * DT * DT, DT, DT, 1);
    gemm_tc<true, false><<<gp, 256, SMEM_DYN>>>(tA, tB, Kv, Wk_v_b, 0);
    enc3d(&tB, Wr + 2L * DT * DT, DT, DT, 1);
    gemm_tc<true, true ><<<gp, 256, SMEM_DYN>>>(tA, tB, VvT, Wv_v_b, 0);

    enc3d(&tA, oTr, DT, BATCH * SEQ, 1);
    enc3d(&tB, Wr + 3L * DT * DT, DT, DT, 1);
    gemm_tc<true, false><<<gp, 256, SMEM_DYN>>>(tA, tB, Kt, Wk_t_b, 0);
    enc3d(&tB, Wr + 4L * DT * DT, DT, DT, 1);
    gemm_tc<true, true ><<<gp, 256, SMEM_DYN>>>(tA, tB, VtT, Wv_t_b, 0);
    enc3d(&tB, Wr + 5L * DT * DT, DT, DT, 1);
    gemm_tc<true, false><<<gp, 256, SMEM_DYN>>>(tA, tB, Qt, Wq_t_b, 0);

    const long S1 = (long)SEQ * SEQ;

    // 3) sim -> mask -> maskT
    enc3d(&tA, oVr, DT, SEQ, BATCH);
    enc3d(&tB, oTr, DT, SEQ, BATCH);
    gemm_tc<false, false><<<gb, 256, SMEM_DYN>>>(tA, tB, Ssc, nullptr, S1);
    mask_kernel<<<dim3(SEQ, BATCH), 256>>>(Ssc, lv, maskO);
    transpose_kernel<<<dim3(32, 32, BATCH), dim3(32, 32)>>>(maskO, maskT);

    // 4) V->T attention
    enc3d(&tA, Qv, DT, SEQ, BATCH);
    enc3d(&tB, Kt, DT, SEQ, BATCH);
    gemm_tc<false, false><<<gb, 256, SMEM_DYN>>>(tA, tB, Ssc, nullptr, S1);
    msoftmax_kernel<<<dim3(SEQ, BATCH), 256>>>(Ssc, maskO);
    enc3d(&tA, Ssc, SEQ, SEQ, BATCH);
    enc3d(&tB, VtT, SEQ, DT, BATCH);
    gemm_tc<false, false><<<gb, 256, SMEM_DYN>>>(tA, tB, out_vt, nullptr, S1);

    // 5) T->V attention
    enc3d(&tA, Qt, DT, SEQ, BATCH);
    enc3d(&tB, Kv, DT, SEQ, BATCH);
    gemm_tc<false, false><<<gb, 256, SMEM_DYN>>>(tA, tB, Ssc, nullptr, S1);
    msoftmax_kernel<<<dim3(SEQ, BATCH), 256>>>(Ssc, maskT);
    enc3d(&tA, Ssc, SEQ, SEQ, BATCH);
    enc3d(&tB, VvT, SEQ, DT, BATCH);
    gemm_tc<false, false><<<gb, 256, SMEM_DYN>>>(tA, tB, out_tv, nullptr, S1);
}

// round 7
// speedup vs baseline: 2.8133x; 1.0748x over previous
#include <cuda_runtime.h>
#include <cuda.h>
#include <cstdint>

// ===========================================================================
#define BATCH 16
#define SEQ   1024
#define DT    1024
#define HID   512
#define NEG_INF_F (-1.0e9f)
static __device__ __host__ constexpr float INV_SQRT = 0.03125f;

static constexpr long ELEM1 = 16LL * 1024 * 1024;
__device__ __align__(1024) float g_scr[ELEM1 * 10 + 6L * DT * DT + 2 * BATCH * DT + 64];

// ===========================================================================
// PTX helpers
// ===========================================================================
__device__ __forceinline__ uint32_t smem_u32(const void* p) {
    uint32_t a;
    asm("{ .reg .u64 t; cvta.to.shared.u64 t, %1; cvt.u32.u64 %0, t; }" : "=r"(a) : "l"(p));
    return a;
}
__device__ __forceinline__ uint32_t lds_u(uint32_t a) {
    uint32_t v;
    asm volatile("ld.shared.b32 %0, [%1];" : "=r"(v) : "r"(a));
    return v;
}
__device__ __forceinline__ float rnd_tf32(float f) {
    uint32_t r;
    asm volatile("cvt.rna.tf32.f32 %0, %1;" : "=r"(r) : "f"(f));
    return __uint_as_float(r);
}

#define MBARRIER_INIT(mbar, count) \
    asm volatile("mbarrier.init.shared.b64 [%0], %1;" :: "r"((uint32_t)(mbar)), "r"((uint32_t)(count)) : "memory")
#define MBARRIER_EXPECT_TX(mbar, bytes) \
    asm volatile("mbarrier.arrive.expect_tx.shared.b64 _, [%0], %1;" \
        :: "r"((uint32_t)(mbar)), "r"((uint32_t)(bytes)) : "memory")
#define MBARRIER_ARRIVE(mbar) \
    asm volatile("mbarrier.arrive.release.cta.shared.b64 _, [%0];" :: "r"((uint32_t)(mbar)) : "memory")
#define MBARRIER_WAIT_PARITY(mbar, parity) do {                                  \
    uint32_t _m = (uint32_t)(mbar);  uint32_t _p = (uint32_t)(parity);           \
    asm volatile(                                                                 \
        "{\n\t.reg .pred P1;\n\t"                                                 \
        "WL_%=:\n\t"                                                              \
        "mbarrier.try_wait.parity.acquire.cta.shared::cta.b64 P1, [%0], %1, 0x989680;\n\t" \
        "@P1 bra.uni WD_%=;\n\t"                                                  \
        "bra.uni WL_%=;\n\t"                                                      \
        "WD_%=:\n\t}"                                                             \
        :: "r"(_m), "r"(_p) : "memory");                                          \
} while (0)
#define TMA_LOAD_3D(saddr, tmap, cx, cy, cz, mbar) \
    asm volatile( \
        "cp.async.bulk.tensor.3d.shared::cta.global.tile.mbarrier::complete_tx::bytes " \
        "[%0], [%1, {%2, %3, %4}], [%5];" \
        :: "r"((uint32_t)(saddr)), "l"(tmap), "r"((int)(cx)), "r"((int)(cy)), "r"((int)(cz)), \
           "r"((uint32_t)(mbar)) : "memory")

// ===========================================================================
// TMA + mma.m16n8k8.tf32 GEMM:  C[M,N] = A[M,K] @ B[N,K]^T (+bias)
// CTA tile 128x128, KT=32 per stage, 3 stages, 256 threads.
// Full/empty mbarrier ring (no per-tile __syncthreads) — warps decoupled.
// ===========================================================================
static constexpr int BM = 128, BN = 128, KT = 32, STAGES = 3;
static constexpr int ABYT = BM * KT * 4;
static constexpr int BBYT = BN * KT * 4;
static constexpr int STB  = ABYT + BBYT;               // 32768
static constexpr int SMEM_DYN = 1024 + STAGES * STB;   // 99328

template <bool BIAS, bool TRANSOUT>
__global__ void __launch_bounds__(256, 2)
gemm_tc(const __grid_constant__ CUtensorMap tmA,
        const __grid_constant__ CUtensorMap tmB,
        float* __restrict__ C, const float* __restrict__ bias, long sCz)
{
    extern __shared__ char dynraw[];
    __shared__ __align__(8) unsigned long long mb[2 * STAGES];  // [0..2]=full, [3..5]=empty

    uint32_t d0 = smem_u32(dynraw);
    uint32_t sb = (d0 + 1023u) & ~1023u;

    const int tid  = threadIdx.x;
    const int warp = tid >> 5, lane = tid & 31;
    const int wm = warp & 3, wn = warp >> 2;
    const int gID = lane >> 2, tig = lane & 3;
    const int m0 = blockIdx.y * BM, n0 = blockIdx.x * BN, z = blockIdx.z;
    const uint32_t mbase = smem_u32(mb);
#define FULLB(s)  (mbase + 8 * (s))
#define EMPTYB(s) (mbase + 24 + 8 * (s))

    if (tid == 0) {
        for (int s = 0; s < STAGES; s++) {
            MBARRIER_INIT(FULLB(s), 1);
            MBARRIER_INIT(EMPTYB(s), 8);
        }
    }
    __syncthreads();

    // prologue: fill all 3 stages
    if (tid == 0) {
        for (int s = 0; s < STAGES; s++) {
            MBARRIER_EXPECT_TX(FULLB(s), STB);
            TMA_LOAD_3D(sb + s * STB,        &tmA, s * KT, m0, z, FULLB(s));
            TMA_LOAD_3D(sb + s * STB + ABYT, &tmB, s * KT, n0, z, FULLB(s));
        }
    }

    float acc[2][8][4];
#pragma unroll
    for (int mi = 0; mi < 2; mi++)
#pragma unroll
        for (int ni = 0; ni < 8; ni++)
#pragma unroll
            for (int e = 0; e < 4; e++) acc[mi][ni][e] = 0.0f;

    const uint32_t gx   = (uint32_t)gID << 4;
    const uint32_t rowA = (uint32_t)(wm * 32 + gID) * 128;
    const uint32_t rowB = (uint32_t)(wn * 64 + gID) * 128;
    const int NKT = 32;   // K = 1024

    int s = 0, ph = 0;    // stage and phase trackers (wrap at 3)
    for (int kt = 0; kt < NKT; kt++) {
        const uint32_t stg = sb + s * STB;
        MBARRIER_WAIT_PARITY(FULLB(s), ph);

        const uint32_t aBase = stg + rowA;
        const uint32_t bBase = stg + ABYT + rowB;

#pragma unroll
        for (int kk = 0; kk < 4; kk++) {
            const uint32_t off0 = ((uint32_t)(kk * 32 + tig * 4)) ^ gx;
            const uint32_t off1 = off0 ^ 16u;

            uint32_t ua[2][4], ub[8][2];
#pragma unroll
            for (int mi = 0; mi < 2; mi++) {
                ua[mi][0] = lds_u(aBase + mi * 2048 + off0);
                ua[mi][1] = lds_u(aBase + mi * 2048 + 1024 + off0);
                ua[mi][2] = lds_u(aBase + mi * 2048 + off1);
                ua[mi][3] = lds_u(aBase + mi * 2048 + 1024 + off1);
            }
#pragma unroll
            for (int ni = 0; ni < 8; ni++) {
                ub[ni][0] = lds_u(bBase + ni * 1024 + off0);
                ub[ni][1] = lds_u(bBase + ni * 1024 + off1);
            }
#pragma unroll
            for (int mi = 0; mi < 2; mi++)
#pragma unroll
                for (int ni = 0; ni < 8; ni++)
                    asm volatile(
                        "mma.sync.aligned.m16n8k8.row.col.f32.tf32.tf32.f32 "
                        "{%0,%1,%2,%3},{%4,%5,%6,%7},{%8,%9},{%0,%1,%2,%3};"
                        : "+f"(acc[mi][ni][0]), "+f"(acc[mi][ni][1]),
                          "+f"(acc[mi][ni][2]), "+f"(acc[mi][ni][3])
                        : "r"(ua[mi][0]), "r"(ua[mi][1]), "r"(ua[mi][2]), "r"(ua[mi][3]),
                          "r"(ub[ni][0]), "r"(ub[ni][1]));
        }

        // consumer done with stage s
        __syncwarp();
        if (lane == 0) MBARRIER_ARRIVE(EMPTYB(s));

        // producer: refill stage s for tile kt+3 once all warps are done with it
        if (tid == 0 && kt + STAGES < NKT) {
            MBARRIER_WAIT_PARITY(EMPTYB(s), ph);
            MBARRIER_EXPECT_TX(FULLB(s), STB);
            TMA_LOAD_3D(sb + s * STB,        &tmA, (kt + STAGES) * KT, m0, z, FULLB(s));
            TMA_LOAD_3D(sb + s * STB + ABYT, &tmB, (kt + STAGES) * KT, n0, z, FULLB(s));
        }

        if (++s == STAGES) { s = 0; ph ^= 1; }
    }
    __syncthreads();   // all compute done; stage memory reusable for epilogue

    // ---- epilogue (reuse stage SMEM as staging tile) ----
    float* ep = (float*)(dynraw + (sb - d0));
    if (BIAS) {
#pragma unroll
        for (int ni = 0; ni < 8; ni++) {
            const int nc = n0 + wn * 64 + ni * 8 + 2 * tig;
            const float b0 = __ldg(bias + nc), b1 = __ldg(bias + nc + 1);
#pragma unroll
            for (int mi = 0; mi < 2; mi++) {
                acc[mi][ni][0] = rnd_tf32(acc[mi][ni][0] + b0);
                acc[mi][ni][1] = rnd_tf32(acc[mi][ni][1] + b1);
                acc[mi][ni][2] = rnd_tf32(acc[mi][ni][2] + b0);
                acc[mi][ni][3] = rnd_tf32(acc[mi][ni][3] + b1);
            }
        }
    }

    if (!TRANSOUT) {
        const int P = 132;
#pragma unroll
        for (int mi = 0; mi < 2; mi++)
#pragma unroll
            for (int ni = 0; ni < 8; ni++) {
                const int r = wm * 32 + mi * 16 + gID;
                const int c = wn * 64 + ni * 8 + 2 * tig;
                *(float2*)(ep + r * P + c)       = make_float2(acc[mi][ni][0], acc[mi][ni][1]);
                *(float2*)(ep + (r + 8) * P + c) = make_float2(acc[mi][ni][2], acc[mi][ni][3]);
            }
        __syncthreads();
        float* Cz = C + (long)z * sCz;
#pragma unroll
        for (int it = 0; it < 16; it++) {
            const int idx = tid + it * 256;
            const int r = idx >> 5, c4 = (idx & 31) * 4;
            float4 v = *(float4*)(ep + r * P + c4);
            *(float4*)(Cz + (long)(m0 + r) * 1024 + n0 + c4) = v;
        }
    } else {
        const int P = 129;
#pragma unroll
        for (int mi = 0; mi < 2; mi++)
#pragma unroll
            for (int ni = 0; ni < 8; ni++) {
                const int r = wm * 32 + mi * 16 + gID;
                const int c = wn * 64 + ni * 8 + 2 * tig;
                ep[r * P + c]           = acc[mi][ni][0];
                ep[r * P + c + 1]       = acc[mi][ni][1];
                ep[(r + 8) * P + c]     = acc[mi][ni][2];
                ep[(r + 8) * P + c + 1] = acc[mi][ni][3];
            }
        __syncthreads();
        const int b  = m0 >> 10;
        const int mlb = m0 & 1023;
#pragma unroll
        for (int it = 0; it < 64; it++) {
            const int idx = tid + it * 256;
            const int n = idx >> 7, m = idx & 127;
            C[((long)b << 20) + (long)(n0 + n) * 1024 + (mlb + m)] = ep[m * P + n];
        }
    }
#undef FULLB
#undef EMPTYB
}

// ===========================================================================
// Pre-round to tf32 (rna), vectorized
// ===========================================================================
__global__ void round_kernel(const float4* __restrict__ in, float4* __restrict__ out, long n4)
{
    long i = (long)blockIdx.x * blockDim.x + threadIdx.x;
    long stride = (long)gridDim.x * blockDim.x;
    for (; i < n4; i += stride) {
        float4 v = in[i];
        v.x = rnd_tf32(v.x); v.y = rnd_tf32(v.y);
        v.z = rnd_tf32(v.z); v.w = rnd_tf32(v.w);
        out[i] = v;
    }
}

// ===========================================================================
// Elementwise kernels
// ===========================================================================
__global__ void pool_kernel(const float* __restrict__ src, float* __restrict__ dst)
{
    int b = blockIdx.y;
    int d = blockIdx.x * 256 + threadIdx.x;
    const float* p = src + ((long)b << 20) + d;
    float s = 0.f;
#pragma unroll 8
    for (int m = 0; m < SEQ; m++) s += p[(long)m << 10];
    dst[b * DT + d] = s * (1.0f / 1024.0f);
}

__global__ void ffn_kernel(const float* __restrict__ poolV, const float* __restrict__ poolT,
                           const float* __restrict__ w1, const float* __restrict__ b1,
                           const float* __restrict__ w2, const float* __restrict__ b2,
                           float* __restrict__ lout)
{
    __shared__ float x[2 * DT];
    __shared__ float red[HID];
    int b = blockIdx.x, t = threadIdx.x;
    for (int i = t; i < 2 * DT; i += HID)
        x[i] = (i < DT) ? poolV[b * DT + i] : poolT[b * DT + (i - DT)];
    __syncthreads();
    float acc = b1[t];
    const float* wr = w1 + (long)t * (2 * DT);
#pragma unroll 8
    for (int k = 0; k < 2 * DT; k++) acc += wr[k] * x[k];
    float h = fmaxf(acc, 0.0f);
    red[t] = h * w2[t];
    __syncthreads();
    for (int s = HID / 2; s > 0; s >>= 1) {
        if (t < s) red[t] += red[t + s];
        __syncthreads();
    }
    if (t == 0) lout[b] = 1.0f / (1.0f + expf(-(red[0] + b2[0])));
}

__device__ __forceinline__ float block_max(float v, float* red)
{
    int t = threadIdx.x;
    red[t] = v; __syncthreads();
    for (int s = 128; s > 0; s >>= 1) {
        if (t < s) red[t] = fmaxf(red[t], red[t + s]);
        __syncthreads();
    }
    float r = red[0]; __syncthreads();
    return r;
}
__device__ __forceinline__ float block_sum(float v, float* red)
{
    int t = threadIdx.x;
    red[t] = v; __syncthreads();
    for (int s = 128; s > 0; s >>= 1) {
        if (t < s) red[t] += red[t + s];
        __syncthreads();
    }
    float r = red[0]; __syncthreads();
    return r;
}

__global__ void mask_kernel(const float* __restrict__ S, const float* __restrict__ lv,
                            float* __restrict__ maskO)
{
    __shared__ float red[256];
    int t = threadIdx.x;
    long row = (long)blockIdx.y * SEQ + blockIdx.x;
    const float* p = S + row * SEQ;
    float x[4];
    float mx = -3.4e38f;
#pragma unroll
    for (int i = 0; i < 4; i++) {
        x[i] = p[t + i * 256] * INV_SQRT;
        mx = fmaxf(mx, x[i]);
    }
    mx = block_max(mx, red);
    float s = 0.f;
#pragma unroll
    for (int i = 0; i < 4; i++) s += expf(x[i] - mx);
    s = block_sum(s, red);
    float l = lv[blockIdx.y];
    float* o = maskO + row * SEQ;
#pragma unroll
    for (int i = 0; i < 4; i++)
        o[t + i * 256] = ((expf(x[i] - mx) / s) >= l) ? 1.0f : 0.0f;
}

__global__ void msoftmax_kernel(float* __restrict__ S, const float* __restrict__ maskM)
{
    __shared__ float red[256];
    int t = threadIdx.x;
    long row = (long)blockIdx.y * SEQ + blockIdx.x;
    float* p = S + row * SEQ;
    const float* mk = maskM + row * SEQ;
    float x[4];
    float mx = -3.4e38f;
#pragma unroll
    for (int i = 0; i < 4; i++) {
        int idx = t + i * 256;
        x[i] = (mk[idx] != 0.0f) ? p[idx] * INV_SQRT : NEG_INF_F;
        mx = fmaxf(mx, x[i]);
    }
    mx = block_max(mx, red);
    float s = 0.f;
#pragma unroll
    for (int i = 0; i < 4; i++) s += expf(x[i] - mx);
    s = block_sum(s, red);
#pragma unroll
    for (int i = 0; i < 4; i++)
        p[t + i * 256] = rnd_tf32(expf(x[i] - mx) / s);
}

__global__ void transpose_kernel(const float* __restrict__ in, float* __restrict__ out)
{
    __shared__ float tile[32][33];
    long base = (long)blockIdx.z << 20;
    int m = blockIdx.y * 32 + threadIdx.y;
    int n = blockIdx.x * 32 + threadIdx.x;
    tile[threadIdx.y][threadIdx.x] = in[base + (long)m * SEQ + n];
    __syncthreads();
    int n2 = blockIdx.x * 32 + threadIdx.y;
    int m2 = blockIdx.y * 32 + threadIdx.x;
    out[base + (long)n2 * SEQ + m2] = tile[threadIdx.x][threadIdx.y];
}

// ===========================================================================
// Host side
// ===========================================================================
typedef CUresult (*PFN_encodeTiled)(CUtensorMap*, CUtensorMapDataType, cuuint32_t, void*,
                                    const cuuint64_t*, const cuuint64_t*, const cuuint32_t*,
                                    const cuuint32_t*, CUtensorMapInterleave, CUtensorMapSwizzle,
                                    CUtensorMapL2promotion, CUtensorMapFloatOOBfill);
static PFN_encodeTiled g_enc = nullptr;

static void enc3d(CUtensorMap* tm, const void* p, long K, long R, long Z)
{
    cuuint64_t dims[3] = {(cuuint64_t)K, (cuuint64_t)R, (cuuint64_t)Z};
    cuuint64_t str[2]  = {(cuuint64_t)(K * 4), (cuuint64_t)(K * R * 4)};
    cuuint32_t box[3]  = {(cuuint32_t)KT, 128, 1};
    cuuint32_t es[3]   = {1, 1, 1};
    g_enc(tm, CU_TENSOR_MAP_DATA_TYPE_FLOAT32, 3, (void*)p, dims, str, box, es,
          CU_TENSOR_MAP_INTERLEAVE_NONE, CU_TENSOR_MAP_SWIZZLE_128B,
          CU_TENSOR_MAP_L2_PROMOTION_L2_128B, CU_TENSOR_MAP_FLOAT_OOB_FILL_NONE);
}

extern "C" void kernel_launch(void* const* d_in, const int* in_sizes, int n_in,
                              void* d_out, int out_size)
{
    (void)in_sizes; (void)n_in; (void)out_size;

    const float* oV     = (const float*)d_in[0];
    const float* oT     = (const float*)d_in[1];
    const float* Wq_v_w = (const float*)d_in[2];
    const float* Wq_v_b = (const float*)d_in[3];
    const float* Wk_t_w = (const float*)d_in[4];
    const float* Wk_t_b = (const float*)d_in[5];
    const float* Wv_t_w = (const float*)d_in[6];
    const float* Wv_t_b = (const float*)d_in[7];
    const float* Wq_t_w = (const float*)d_in[8];
    const float* Wq_t_b = (const float*)d_in[9];
    const float* Wk_v_w = (const float*)d_in[10];
    const float* Wk_v_b = (const float*)d_in[11];
    const float* Wv_v_w = (const float*)d_in[12];
    const float* Wv_v_b = (const float*)d_in[13];
    const float* ffn1_w = (const float*)d_in[14];
    const float* ffn1_b = (const float*)d_in[15];
    const float* ffn2_w = (const float*)d_in[16];
    const float* ffn2_b = (const float*)d_in[17];

    float* out_vt = (float*)d_out;
    float* out_tv = out_vt + ELEM1;
    float* maskO  = out_vt + 2 * ELEM1;

    static float* scr = nullptr;
    if (!scr) cudaGetSymbolAddress((void**)&scr, g_scr);
    if (!g_enc) {
        void* p = nullptr;
        cudaDriverEntryPointQueryResult st;
        cudaGetDriverEntryPoint("cuTensorMapEncodeTiled", &p, cudaEnableDefault, &st);
        g_enc = (PFN_encodeTiled)p;
    }
    static bool attr_done = false;
    if (!attr_done) {
        cudaFuncSetAttribute(gemm_tc<true,  false>, cudaFuncAttributeMaxDynamicSharedMemorySize, SMEM_DYN);
        cudaFuncSetAttribute(gemm_tc<true,  true>,  cudaFuncAttributeMaxDynamicSharedMemorySize, SMEM_DYN);
        cudaFuncSetAttribute(gemm_tc<false, false>, cudaFuncAttributeMaxDynamicSharedMemorySize, SMEM_DYN);
        attr_done = true;
    }

    float* Qv    = scr + 0 * ELEM1;
    float* Kt    = scr + 1 * ELEM1;
    float* VtT   = scr + 2 * ELEM1;   // (B, DT, SEQ)
    float* Qt    = scr + 3 * ELEM1;
    float* Kv    = scr + 4 * ELEM1;
    float* VvT   = scr + 5 * ELEM1;   // (B, DT, SEQ)
    float* Ssc   = scr + 6 * ELEM1;
    float* maskT = scr + 7 * ELEM1;
    float* oVr   = scr + 8 * ELEM1;
    float* oTr   = scr + 9 * ELEM1;
    float* Wr    = scr + 10 * ELEM1;
    float* poolV = Wr + 6L * DT * DT;
    float* poolT = poolV + BATCH * DT;
    float* lv    = poolT + BATCH * DT;

    // 0) pre-round GEMM inputs to tf32
    const long N4BIG = ELEM1 / 4;
    round_kernel<<<2048, 256>>>((const float4*)oV, (float4*)oVr, N4BIG);
    round_kernel<<<2048, 256>>>((const float4*)oT, (float4*)oTr, N4BIG);
    const long N4W = (long)DT * DT / 4;
    round_kernel<<<512, 256>>>((const float4*)Wq_v_w, (float4*)(Wr + 0L * DT * DT), N4W);
    round_kernel<<<512, 256>>>((const float4*)Wk_v_w, (float4*)(Wr + 1L * DT * DT), N4W);
    round_kernel<<<512, 256>>>((const float4*)Wv_v_w, (float4*)(Wr + 2L * DT * DT), N4W);
    round_kernel<<<512, 256>>>((const float4*)Wk_t_w, (float4*)(Wr + 3L * DT * DT), N4W);
    round_kernel<<<512, 256>>>((const float4*)Wv_t_w, (float4*)(Wr + 4L * DT * DT), N4W);
    round_kernel<<<512, 256>>>((const float4*)Wq_t_w, (float4*)(Wr + 5L * DT * DT), N4W);

    // 1) pools + gate
    pool_kernel<<<dim3(4, BATCH), 256>>>(oV, poolV);
    pool_kernel<<<dim3(4, BATCH), 256>>>(oT, poolT);
    ffn_kernel<<<BATCH, HID>>>(poolV, poolT, ffn1_w, ffn1_b, ffn2_w, ffn2_b, lv);

    CUtensorMap tA, tB;
    const dim3 gp(8, 128, 1);
    const dim3 gb(8, 8, BATCH);

    // 2) projections
    enc3d(&tA, oVr, DT, BATCH * SEQ, 1);
    enc3d(&tB, Wr + 0L * DT * DT, DT, DT, 1);
    gemm_tc<true, false><<<gp, 256, SMEM_DYN>>>(tA, tB, Qv, Wq_v_b, 0);
    enc3d(&tB, Wr + 1L * DT * DT, DT, DT, 1);
    gemm_tc<true, false><<<gp, 256, SMEM_DYN>>>(tA, tB, Kv, Wk_v_b, 0);
    enc3d(&tB, Wr + 2L * DT * DT, DT, DT, 1);
    gemm_tc<true, true ><<<gp, 256, SMEM_DYN>>>(tA, tB, VvT, Wv_v_b, 0);

    enc3d(&tA, oTr, DT, BATCH * SEQ, 1);
    enc3d(&tB, Wr + 3L * DT * DT, DT, DT, 1);
    gemm_tc<true, false><<<gp, 256, SMEM_DYN>>>(tA, tB, Kt, Wk_t_b, 0);
    enc3d(&tB, Wr + 4L * DT * DT, DT, DT, 1);
    gemm_tc<true, true ><<<gp, 256, SMEM_DYN>>>(tA, tB, VtT, Wv_t_b, 0);
    enc3d(&tB, Wr + 5L * DT * DT, DT, DT, 1);
    gemm_tc<true, false><<<gp, 256, SMEM_DYN>>>(tA, tB, Qt, Wq_t_b, 0);

    const long S1 = (long)SEQ * SEQ;

    // 3) sim -> mask -> maskT
    enc3d(&tA, oVr, DT, SEQ, BATCH);
    enc3d(&tB, oTr, DT, SEQ, BATCH);
    gemm_tc<false, false><<<gb, 256, SMEM_DYN>>>(tA, tB, Ssc, nullptr, S1);
    mask_kernel<<<dim3(SEQ, BATCH), 256>>>(Ssc, lv, maskO);
    transpose_kernel<<<dim3(32, 32, BATCH), dim3(32, 32)>>>(maskO, maskT);

    // 4) V->T attention
    enc3d(&tA, Qv, DT, SEQ, BATCH);
    enc3d(&tB, Kt, DT, SEQ, BATCH);
    gemm_tc<false, false><<<gb, 256, SMEM_DYN>>>(tA, tB, Ssc, nullptr, S1);
    msoftmax_kernel<<<dim3(SEQ, BATCH), 256>>>(Ssc, maskO);
    enc3d(&tA, Ssc, SEQ, SEQ, BATCH);
    enc3d(&tB, VtT, SEQ, DT, BATCH);
    gemm_tc<false, false><<<gb, 256, SMEM_DYN>>>(tA, tB, out_vt, nullptr, S1);

    // 5) T->V attention
    enc3d(&tA, Qt, DT, SEQ, BATCH);
    enc3d(&tB, Kv, DT, SEQ, BATCH);
    gemm_tc<false, false><<<gb, 256, SMEM_DYN>>>(tA, tB, Ssc, nullptr, S1);
    msoftmax_kernel<<<dim3(SEQ, BATCH), 256>>>(Ssc, maskT);
    enc3d(&tA, Ssc, SEQ, SEQ, BATCH);
    enc3d(&tB, VvT, SEQ, DT, BATCH);
    gemm_tc<false, false><<<gb, 256, SMEM_DYN>>>(tA, tB, out_tv, nullptr, S1);
}

// round 8
// speedup vs baseline: 2.8542x; 1.0145x over previous
#include <cuda_runtime.h>
#include <cuda.h>
#include <cstdint>

// ===========================================================================
#define BATCH 16
#define SEQ   1024
#define DT    1024
#define HID   512
#define NEG_INF_F (-1.0e9f)
static __device__ __host__ constexpr float INV_SQRT = 0.03125f;

static constexpr long ELEM1 = 16LL * 1024 * 1024;
__device__ __align__(1024) float g_scr[ELEM1 * 10 + 6L * DT * DT + 2 * BATCH * DT + 64];

// ===========================================================================
// PTX helpers
// ===========================================================================
__device__ __forceinline__ uint32_t smem_u32(const void* p) {
    uint32_t a;
    asm("{ .reg .u64 t; cvta.to.shared.u64 t, %1; cvt.u32.u64 %0, t; }" : "=r"(a) : "l"(p));
    return a;
}
__device__ __forceinline__ uint32_t lds_u(uint32_t a) {
    uint32_t v;
    asm volatile("ld.shared.b32 %0, [%1];" : "=r"(v) : "r"(a));
    return v;
}
__device__ __forceinline__ float rnd_tf32(float f) {
    uint32_t r;
    asm volatile("cvt.rna.tf32.f32 %0, %1;" : "=r"(r) : "f"(f));
    return __uint_as_float(r);
}

#define MBARRIER_INIT(mbar, count) \
    asm volatile("mbarrier.init.shared.b64 [%0], %1;" :: "r"((uint32_t)(mbar)), "r"((uint32_t)(count)) : "memory")
#define MBARRIER_EXPECT_TX(mbar, bytes) \
    asm volatile("mbarrier.arrive.expect_tx.shared.b64 _, [%0], %1;" \
        :: "r"((uint32_t)(mbar)), "r"((uint32_t)(bytes)) : "memory")
#define MBARRIER_ARRIVE(mbar) \
    asm volatile("mbarrier.arrive.release.cta.shared.b64 _, [%0];" :: "r"((uint32_t)(mbar)) : "memory")
#define MBARRIER_WAIT_PARITY(mbar, parity) do {                                  \
    uint32_t _m = (uint32_t)(mbar);  uint32_t _p = (uint32_t)(parity);           \
    asm volatile(                                                                 \
        "{\n\t.reg .pred P1;\n\t"                                                 \
        "WL_%=:\n\t"                                                              \
        "mbarrier.try_wait.parity.acquire.cta.shared::cta.b64 P1, [%0], %1, 0x989680;\n\t" \
        "@P1 bra.uni WD_%=;\n\t"                                                  \
        "bra.uni WL_%=;\n\t"                                                      \
        "WD_%=:\n\t}"                                                             \
        :: "r"(_m), "r"(_p) : "memory");                                          \
} while (0)
#define TMA_LOAD_3D(saddr, tmap, cx, cy, cz, mbar) \
    asm volatile( \
        "cp.async.bulk.tensor.3d.shared::cta.global.tile.mbarrier::complete_tx::bytes " \
        "[%0], [%1, {%2, %3, %4}], [%5];" \
        :: "r"((uint32_t)(saddr)), "l"(tmap), "r"((int)(cx)), "r"((int)(cy)), "r"((int)(cz)), \
           "r"((uint32_t)(mbar)) : "memory")

// ===========================================================================
// TMA + mma.m16n8k8.tf32 GEMM:  C[M,N] = A[M,K] @ B[N,K]^T (+bias)
// CTA tile 128x128, KT=32/stage, 3 stages, 128 threads (4 warps, 64x64 each).
// Full/empty mbarrier ring; warps decoupled.
// ===========================================================================
static constexpr int BM = 128, BN = 128, KT = 32, STAGES = 3;
static constexpr int ABYT = BM * KT * 4;
static constexpr int BBYT = BN * KT * 4;
static constexpr int STB  = ABYT + BBYT;               // 32768
static constexpr int SMEM_DYN = 1024 + STAGES * STB;   // 99328
static constexpr int NTHR = 128;

template <bool BIAS, bool TRANSOUT>
__global__ void __launch_bounds__(NTHR, 2)
gemm_tc(const __grid_constant__ CUtensorMap tmA,
        const __grid_constant__ CUtensorMap tmB,
        float* __restrict__ C, const float* __restrict__ bias, long sCz)
{
    extern __shared__ char dynraw[];
    __shared__ __align__(8) unsigned long long mb[2 * STAGES];

    uint32_t d0 = smem_u32(dynraw);
    uint32_t sb = (d0 + 1023u) & ~1023u;

    const int tid  = threadIdx.x;
    const int warp = tid >> 5, lane = tid & 31;
    const int wm = warp & 1, wn = warp >> 1;       // 2x2 warp grid, 64x64 tiles
    const int gID = lane >> 2, tig = lane & 3;
    const int m0 = blockIdx.y * BM, n0 = blockIdx.x * BN, z = blockIdx.z;
    const uint32_t mbase = smem_u32(mb);
#define FULLB(s)  (mbase + 8 * (s))
#define EMPTYB(s) (mbase + 24 + 8 * (s))

    if (tid == 0) {
        for (int s = 0; s < STAGES; s++) {
            MBARRIER_INIT(FULLB(s), 1);
            MBARRIER_INIT(EMPTYB(s), 4);
        }
    }
    __syncthreads();

    if (tid == 0) {
        for (int s = 0; s < STAGES; s++) {
            MBARRIER_EXPECT_TX(FULLB(s), STB);
            TMA_LOAD_3D(sb + s * STB,        &tmA, s * KT, m0, z, FULLB(s));
            TMA_LOAD_3D(sb + s * STB + ABYT, &tmB, s * KT, n0, z, FULLB(s));
        }
    }

    float acc[4][8][4];
#pragma unroll
    for (int mi = 0; mi < 4; mi++)
#pragma unroll
        for (int ni = 0; ni < 8; ni++)
#pragma unroll
            for (int e = 0; e < 4; e++) acc[mi][ni][e] = 0.0f;

    const uint32_t gx   = (uint32_t)gID << 4;
    const uint32_t rowA = (uint32_t)(wm * 64 + gID) * 128;
    const uint32_t rowB = (uint32_t)(wn * 64 + gID) * 128;
    const int NKT = 32;   // K = 1024

    int s = 0, ph = 0;
    for (int kt = 0; kt < NKT; kt++) {
        const uint32_t stg = sb + s * STB;
        MBARRIER_WAIT_PARITY(FULLB(s), ph);

        const uint32_t aBase = stg + rowA;
        const uint32_t bBase = stg + ABYT + rowB;

#pragma unroll
        for (int kk = 0; kk < 4; kk++) {
            const uint32_t off0 = ((uint32_t)(kk * 32 + tig * 4)) ^ gx;
            const uint32_t off1 = off0 ^ 16u;

            uint32_t ua[4][4], ub[8][2];
#pragma unroll
            for (int mi = 0; mi < 4; mi++) {
                ua[mi][0] = lds_u(aBase + mi * 2048 + off0);
                ua[mi][1] = lds_u(aBase + mi * 2048 + 1024 + off0);
                ua[mi][2] = lds_u(aBase + mi * 2048 + off1);
                ua[mi][3] = lds_u(aBase + mi * 2048 + 1024 + off1);
            }
#pragma unroll
            for (int ni = 0; ni < 8; ni++) {
                ub[ni][0] = lds_u(bBase + ni * 1024 + off0);
                ub[ni][1] = lds_u(bBase + ni * 1024 + off1);
            }
#pragma unroll
            for (int mi = 0; mi < 4; mi++)
#pragma unroll
                for (int ni = 0; ni < 8; ni++)
                    asm volatile(
                        "mma.sync.aligned.m16n8k8.row.col.f32.tf32.tf32.f32 "
                        "{%0,%1,%2,%3},{%4,%5,%6,%7},{%8,%9},{%0,%1,%2,%3};"
                        : "+f"(acc[mi][ni][0]), "+f"(acc[mi][ni][1]),
                          "+f"(acc[mi][ni][2]), "+f"(acc[mi][ni][3])
                        : "r"(ua[mi][0]), "r"(ua[mi][1]), "r"(ua[mi][2]), "r"(ua[mi][3]),
                          "r"(ub[ni][0]), "r"(ub[ni][1]));
        }

        __syncwarp();
        if (lane == 0) MBARRIER_ARRIVE(EMPTYB(s));

        if (tid == 0 && kt + STAGES < NKT) {
            MBARRIER_WAIT_PARITY(EMPTYB(s), ph);
            MBARRIER_EXPECT_TX(FULLB(s), STB);
            TMA_LOAD_3D(sb + s * STB,        &tmA, (kt + STAGES) * KT, m0, z, FULLB(s));
            TMA_LOAD_3D(sb + s * STB + ABYT, &tmB, (kt + STAGES) * KT, n0, z, FULLB(s));
        }

        if (++s == STAGES) { s = 0; ph ^= 1; }
    }
    __syncthreads();

    // ---- epilogue ----
    float* ep = (float*)(dynraw + (sb - d0));
    if (BIAS) {
#pragma unroll
        for (int ni = 0; ni < 8; ni++) {
            const int nc = n0 + wn * 64 + ni * 8 + 2 * tig;
            const float b0 = __ldg(bias + nc), b1 = __ldg(bias + nc + 1);
#pragma unroll
            for (int mi = 0; mi < 4; mi++) {
                acc[mi][ni][0] = rnd_tf32(acc[mi][ni][0] + b0);
                acc[mi][ni][1] = rnd_tf32(acc[mi][ni][1] + b1);
                acc[mi][ni][2] = rnd_tf32(acc[mi][ni][2] + b0);
                acc[mi][ni][3] = rnd_tf32(acc[mi][ni][3] + b1);
            }
        }
    }

    if (!TRANSOUT) {
        const int P = 132;
#pragma unroll
        for (int mi = 0; mi < 4; mi++)
#pragma unroll
            for (int ni = 0; ni < 8; ni++) {
                const int r = wm * 64 + mi * 16 + gID;
                const int c = wn * 64 + ni * 8 + 2 * tig;
                *(float2*)(ep + r * P + c)       = make_float2(acc[mi][ni][0], acc[mi][ni][1]);
                *(float2*)(ep + (r + 8) * P + c) = make_float2(acc[mi][ni][2], acc[mi][ni][3]);
            }
        __syncthreads();
        float* Cz = C + (long)z * sCz;
#pragma unroll
        for (int it = 0; it < 32; it++) {
            const int idx = tid + it * NTHR;
            const int r = idx >> 5, c4 = (idx & 31) * 4;
            float4 v = *(float4*)(ep + r * P + c4);
            *(float4*)(Cz + (long)(m0 + r) * 1024 + n0 + c4) = v;
        }
    } else {
        const int P = 129;
#pragma unroll
        for (int mi = 0; mi < 4; mi++)
#pragma unroll
            for (int ni = 0; ni < 8; ni++) {
                const int r = wm * 64 + mi * 16 + gID;
                const int c = wn * 64 + ni * 8 + 2 * tig;
                ep[r * P + c]           = acc[mi][ni][0];
                ep[r * P + c + 1]       = acc[mi][ni][1];
                ep[(r + 8) * P + c]     = acc[mi][ni][2];
                ep[(r + 8) * P + c + 1] = acc[mi][ni][3];
            }
        __syncthreads();
        const int b  = m0 >> 10;
        const int mlb = m0 & 1023;
#pragma unroll 8
        for (int it = 0; it < 128; it++) {
            const int idx = tid + it * NTHR;
            const int n = idx >> 7, m = idx & 127;
            C[((long)b << 20) + (long)(n0 + n) * 1024 + (mlb + m)] = ep[m * P + n];
        }
    }
#undef FULLB
#undef EMPTYB
}

// ===========================================================================
// Pre-round to tf32
// ===========================================================================
__global__ void round_kernel(const float4* __restrict__ in, float4* __restrict__ out, long n4)
{
    long i = (long)blockIdx.x * blockDim.x + threadIdx.x;
    long stride = (long)gridDim.x * blockDim.x;
    for (; i < n4; i += stride) {
        float4 v = in[i];
        v.x = rnd_tf32(v.x); v.y = rnd_tf32(v.y);
        v.z = rnd_tf32(v.z); v.w = rnd_tf32(v.w);
        out[i] = v;
    }
}

struct Ptr6 { const float4* in[6]; };
__global__ void round6_kernel(Ptr6 p, float4* __restrict__ out, long n4each)
{
    const float4* in = p.in[blockIdx.y];
    float4* o = out + blockIdx.y * n4each;
    long i = (long)blockIdx.x * blockDim.x + threadIdx.x;
    long stride = (long)gridDim.x * blockDim.x;
    for (; i < n4each; i += stride) {
        float4 v = in[i];
        v.x = rnd_tf32(v.x); v.y = rnd_tf32(v.y);
        v.z = rnd_tf32(v.z); v.w = rnd_tf32(v.w);
        o[i] = v;
    }
}

// ===========================================================================
// Elementwise kernels
// ===========================================================================
__global__ void pool_kernel(const float* __restrict__ src, float* __restrict__ dst)
{
    int b = blockIdx.y;
    int d = blockIdx.x * 256 + threadIdx.x;
    const float* p = src + ((long)b << 20) + d;
    float s = 0.f;
#pragma unroll 8
    for (int m = 0; m < SEQ; m++) s += p[(long)m << 10];
    dst[b * DT + d] = s * (1.0f / 1024.0f);
}

__global__ void ffn_kernel(const float* __restrict__ poolV, const float* __restrict__ poolT,
                           const float* __restrict__ w1, const float* __restrict__ b1,
                           const float* __restrict__ w2, const float* __restrict__ b2,
                           float* __restrict__ lout)
{
    __shared__ float x[2 * DT];
    __shared__ float red[HID];
    int b = blockIdx.x, t = threadIdx.x;
    for (int i = t; i < 2 * DT; i += HID)
        x[i] = (i < DT) ? poolV[b * DT + i] : poolT[b * DT + (i - DT)];
    __syncthreads();
    float acc = b1[t];
    const float* wr = w1 + (long)t * (2 * DT);
#pragma unroll 8
    for (int k = 0; k < 2 * DT; k++) acc += wr[k] * x[k];
    float h = fmaxf(acc, 0.0f);
    red[t] = h * w2[t];
    __syncthreads();
    for (int s = HID / 2; s > 0; s >>= 1) {
        if (t < s) red[t] += red[t + s];
        __syncthreads();
    }
    if (t == 0) lout[b] = 1.0f / (1.0f + expf(-(red[0] + b2[0])));
}

__device__ __forceinline__ float block_max(float v, float* red)
{
    int t = threadIdx.x;
    red[t] = v; __syncthreads();
    for (int s = 128; s > 0; s >>= 1) {
        if (t < s) red[t] = fmaxf(red[t], red[t + s]);
        __syncthreads();
    }
    float r = red[0]; __syncthreads();
    return r;
}
__device__ __forceinline__ float block_sum(float v, float* red)
{
    int t = threadIdx.x;
    red[t] = v; __syncthreads();
    for (int s = 128; s > 0; s >>= 1) {
        if (t < s) red[t] += red[t + s];
        __syncthreads();
    }
    float r = red[0]; __syncthreads();
    return r;
}

__global__ void mask_kernel(const float* __restrict__ S, const float* __restrict__ lv,
                            float* __restrict__ maskO)
{
    __shared__ float red[256];
    int t = threadIdx.x;
    long row = (long)blockIdx.y * SEQ + blockIdx.x;
    const float* p = S + row * SEQ;
    float x[4];
    float mx = -3.4e38f;
#pragma unroll
    for (int i = 0; i < 4; i++) {
        x[i] = p[t + i * 256] * INV_SQRT;
        mx = fmaxf(mx, x[i]);
    }
    mx = block_max(mx, red);
    float s = 0.f;
#pragma unroll
    for (int i = 0; i < 4; i++) s += expf(x[i] - mx);
    s = block_sum(s, red);
    float l = lv[blockIdx.y];
    float* o = maskO + row * SEQ;
#pragma unroll
    for (int i = 0; i < 4; i++)
        o[t + i * 256] = ((expf(x[i] - mx) / s) >= l) ? 1.0f : 0.0f;
}

__global__ void msoftmax_kernel(float* __restrict__ S, const float* __restrict__ maskM)
{
    __shared__ float red[256];
    int t = threadIdx.x;
    long row = (long)blockIdx.y * SEQ + blockIdx.x;
    float* p = S + row * SEQ;
    const float* mk = maskM + row * SEQ;
    float x[4];
    float mx = -3.4e38f;
#pragma unroll
    for (int i = 0; i < 4; i++) {
        int idx = t + i * 256;
        x[i] = (mk[idx] != 0.0f) ? p[idx] * INV_SQRT : NEG_INF_F;
        mx = fmaxf(mx, x[i]);
    }
    mx = block_max(mx, red);
    float s = 0.f;
#pragma unroll
    for (int i = 0; i < 4; i++) s += expf(x[i] - mx);
    s = block_sum(s, red);
#pragma unroll
    for (int i = 0; i < 4; i++)
        p[t + i * 256] = rnd_tf32(expf(x[i] - mx) / s);
}

__global__ void transpose_kernel(const float* __restrict__ in, float* __restrict__ out)
{
    __shared__ float tile[32][33];
    long base = (long)blockIdx.z << 20;
    int m = blockIdx.y * 32 + threadIdx.y;
    int n = blockIdx.x * 32 + threadIdx.x;
    tile[threadIdx.y][threadIdx.x] = in[base + (long)m * SEQ + n];
    __syncthreads();
    int n2 = blockIdx.x * 32 + threadIdx.y;
    int m2 = blockIdx.y * 32 + threadIdx.x;
    out[base + (long)n2 * SEQ + m2] = tile[threadIdx.x][threadIdx.y];
}

// ===========================================================================
// Host side
// ===========================================================================
typedef CUresult (*PFN_encodeTiled)(CUtensorMap*, CUtensorMapDataType, cuuint32_t, void*,
                                    const cuuint64_t*, const cuuint64_t*, const cuuint32_t*,
                                    const cuuint32_t*, CUtensorMapInterleave, CUtensorMapSwizzle,
                                    CUtensorMapL2promotion, CUtensorMapFloatOOBfill);
static PFN_encodeTiled g_enc = nullptr;

static void enc3d(CUtensorMap* tm, const void* p, long K, long R, long Z)
{
    cuuint64_t dims[3] = {(cuuint64_t)K, (cuuint64_t)R, (cuuint64_t)Z};
    cuuint64_t str[2]  = {(cuuint64_t)(K * 4), (cuuint64_t)(K * R * 4)};
    cuuint32_t box[3]  = {(cuuint32_t)KT, 128, 1};
    cuuint32_t es[3]   = {1, 1, 1};
    g_enc(tm, CU_TENSOR_MAP_DATA_TYPE_FLOAT32, 3, (void*)p, dims, str, box, es,
          CU_TENSOR_MAP_INTERLEAVE_NONE, CU_TENSOR_MAP_SWIZZLE_128B,
          CU_TENSOR_MAP_L2_PROMOTION_L2_128B, CU_TENSOR_MAP_FLOAT_OOB_FILL_NONE);
}

extern "C" void kernel_launch(void* const* d_in, const int* in_sizes, int n_in,
                              void* d_out, int out_size)
{
    (void)in_sizes; (void)n_in; (void)out_size;

    const float* oV     = (const float*)d_in[0];
    const float* oT     = (const float*)d_in[1];
    const float* Wq_v_w = (const float*)d_in[2];
    const float* Wq_v_b = (const float*)d_in[3];
    const float* Wk_t_w = (const float*)d_in[4];
    const float* Wk_t_b = (const float*)d_in[5];
    const float* Wv_t_w = (const float*)d_in[6];
    const float* Wv_t_b = (const float*)d_in[7];
    const float* Wq_t_w = (const float*)d_in[8];
    const float* Wq_t_b = (const float*)d_in[9];
    const float* Wk_v_w = (const float*)d_in[10];
    const float* Wk_v_b = (const float*)d_in[11];
    const float* Wv_v_w = (const float*)d_in[12];
    const float* Wv_v_b = (const float*)d_in[13];
    const float* ffn1_w = (const float*)d_in[14];
    const float* ffn1_b = (const float*)d_in[15];
    const float* ffn2_w = (const float*)d_in[16];
    const float* ffn2_b = (const float*)d_in[17];

    float* out_vt = (float*)d_out;
    float* out_tv = out_vt + ELEM1;
    float* maskO  = out_vt + 2 * ELEM1;

    static float* scr = nullptr;
    if (!scr) cudaGetSymbolAddress((void**)&scr, g_scr);
    if (!g_enc) {
        void* p = nullptr;
        cudaDriverEntryPointQueryResult st;
        cudaGetDriverEntryPoint("cuTensorMapEncodeTiled", &p, cudaEnableDefault, &st);
        g_enc = (PFN_encodeTiled)p;
    }
    static bool attr_done = false;
    if (!attr_done) {
        cudaFuncSetAttribute(gemm_tc<true,  false>, cudaFuncAttributeMaxDynamicSharedMemorySize, SMEM_DYN);
        cudaFuncSetAttribute(gemm_tc<true,  true>,  cudaFuncAttributeMaxDynamicSharedMemorySize, SMEM_DYN);
        cudaFuncSetAttribute(gemm_tc<false, false>, cudaFuncAttributeMaxDynamicSharedMemorySize, SMEM_DYN);
        attr_done = true;
    }

    float* Qv    = scr + 0 * ELEM1;
    float* Kt    = scr + 1 * ELEM1;
    float* VtT   = scr + 2 * ELEM1;   // (B, DT, SEQ)
    float* Qt    = scr + 3 * ELEM1;
    float* Kv    = scr + 4 * ELEM1;
    float* VvT   = scr + 5 * ELEM1;   // (B, DT, SEQ)
    float* Ssc   = scr + 6 * ELEM1;
    float* maskT = scr + 7 * ELEM1;
    float* oVr   = scr + 8 * ELEM1;
    float* oTr   = scr + 9 * ELEM1;
    float* Wr    = scr + 10 * ELEM1;
    float* poolV = Wr + 6L * DT * DT;
    float* poolT = poolV + BATCH * DT;
    float* lv    = poolT + BATCH * DT;

    // 0) pre-round GEMM inputs to tf32
    const long N4BIG = ELEM1 / 4;
    round_kernel<<<2048, 256>>>((const float4*)oV, (float4*)oVr, N4BIG);
    round_kernel<<<2048, 256>>>((const float4*)oT, (float4*)oTr, N4BIG);
    Ptr6 wp;
    wp.in[0] = (const float4*)Wq_v_w;  wp.in[1] = (const float4*)Wk_v_w;
    wp.in[2] = (const float4*)Wv_v_w;  wp.in[3] = (const float4*)Wk_t_w;
    wp.in[4] = (const float4*)Wv_t_w;  wp.in[5] = (const float4*)Wq_t_w;
    round6_kernel<<<dim3(256, 6), 256>>>(wp, (float4*)Wr, (long)DT * DT / 4);

    // 1) pools + gate
    pool_kernel<<<dim3(4, BATCH), 256>>>(oV, poolV);
    pool_kernel<<<dim3(4, BATCH), 256>>>(oT, poolT);
    ffn_kernel<<<BATCH, HID>>>(poolV, poolT, ffn1_w, ffn1_b, ffn2_w, ffn2_b, lv);

    CUtensorMap tA, tB;
    const dim3 gp(8, 128, 1);
    const dim3 gb(8, 8, BATCH);

    // 2) projections
    enc3d(&tA, oVr, DT, BATCH * SEQ, 1);
    enc3d(&tB, Wr + 0L * DT * DT, DT, DT, 1);
    gemm_tc<true, false><<<gp, NTHR, SMEM_DYN>>>(tA, tB, Qv, Wq_v_b, 0);
    enc3d(&tB, Wr + 1L * DT * DT, DT, DT, 1);
    gemm_tc<true, false><<<gp, NTHR, SMEM_DYN>>>(tA, tB, Kv, Wk_v_b, 0);
    enc3d(&tB, Wr + 2L * DT * DT, DT, DT, 1);
    gemm_tc<true, true ><<<gp, NTHR, SMEM_DYN>>>(tA, tB, VvT, Wv_v_b, 0);

    enc3d(&tA, oTr, DT, BATCH * SEQ, 1);
    enc3d(&tB, Wr + 3L * DT * DT, DT, DT, 1);
    gemm_tc<true, false><<<gp, NTHR, SMEM_DYN>>>(tA, tB, Kt, Wk_t_b, 0);
    enc3d(&tB, Wr + 4L * DT * DT, DT, DT, 1);
    gemm_tc<true, true ><<<gp, NTHR, SMEM_DYN>>>(tA, tB, VtT, Wv_t_b, 0);
    enc3d(&tB, Wr + 5L * DT * DT, DT, DT, 1);
    gemm_tc<true, false><<<gp, NTHR, SMEM_DYN>>>(tA, tB, Qt, Wq_t_b, 0);

    const long S1 = (long)SEQ * SEQ;

    // 3) sim -> mask -> maskT
    enc3d(&tA, oVr, DT, SEQ, BATCH);
    enc3d(&tB, oTr, DT, SEQ, BATCH);
    gemm_tc<false, false><<<gb, NTHR, SMEM_DYN>>>(tA, tB, Ssc, nullptr, S1);
    mask_kernel<<<dim3(SEQ, BATCH), 256>>>(Ssc, lv, maskO);
    transpose_kernel<<<dim3(32, 32, BATCH), dim3(32, 32)>>>(maskO, maskT);

    // 4) V->T attention
    enc3d(&tA, Qv, DT, SEQ, BATCH);
    enc3d(&tB, Kt, DT, SEQ, BATCH);
    gemm_tc<false, false><<<gb, NTHR, SMEM_DYN>>>(tA, tB, Ssc, nullptr, S1);
    msoftmax_kernel<<<dim3(SEQ, BATCH), 256>>>(Ssc, maskO);
    enc3d(&tA, Ssc, SEQ, SEQ, BATCH);
    enc3d(&tB, VtT, SEQ, DT, BATCH);
    gemm_tc<false, false><<<gb, NTHR, SMEM_DYN>>>(tA, tB, out_vt, nullptr, S1);

    // 5) T->V attention
    enc3d(&tA, Qt, DT, SEQ, BATCH);
    enc3d(&tB, Kv, DT, SEQ, BATCH);
    gemm_tc<false, false><<<gb, NTHR, SMEM_DYN>>>(tA, tB, Ssc, nullptr, S1);
    msoftmax_kernel<<<dim3(SEQ, BATCH), 256>>>(Ssc, maskT);
    enc3d(&tA, Ssc, SEQ, SEQ, BATCH);
    enc3d(&tB, VvT, SEQ, DT, BATCH);
    gemm_tc<false, false><<<gb, NTHR, SMEM_DYN>>>(tA, tB, out_tv, nullptr, S1);
}

// round 9
// speedup vs baseline: 3.0665x; 1.0744x over previous
#include <cuda_runtime.h>
#include <cuda.h>
#include <cstdint>

// ===========================================================================
#define BATCH 16
#define SEQ   1024
#define DT    1024
#define HID   512
#define NEG_INF_F (-1.0e9f)
static __device__ __host__ constexpr float INV_SQRT = 0.03125f;

static constexpr long ELEM1 = 16LL * 1024 * 1024;
__device__ __align__(1024) float g_scr[ELEM1 * 10 + 6L * DT * DT + 400000];

// ===========================================================================
// PTX helpers
// ===========================================================================
__device__ __forceinline__ uint32_t smem_u32(const void* p) {
    uint32_t a;
    asm("{ .reg .u64 t; cvta.to.shared.u64 t, %1; cvt.u32.u64 %0, t; }" : "=r"(a) : "l"(p));
    return a;
}
__device__ __forceinline__ uint32_t lds_u(uint32_t a) {
    uint32_t v;
    asm volatile("ld.shared.b32 %0, [%1];" : "=r"(v) : "r"(a));
    return v;
}
__device__ __forceinline__ float rnd_tf32(float f) {
    uint32_t r;
    asm volatile("cvt.rna.tf32.f32 %0, %1;" : "=r"(r) : "f"(f));
    return __uint_as_float(r);
}

#define MBARRIER_INIT(mbar, count) \
    asm volatile("mbarrier.init.shared.b64 [%0], %1;" :: "r"((uint32_t)(mbar)), "r"((uint32_t)(count)) : "memory")
#define MBARRIER_EXPECT_TX(mbar, bytes) \
    asm volatile("mbarrier.arrive.expect_tx.shared.b64 _, [%0], %1;" \
        :: "r"((uint32_t)(mbar)), "r"((uint32_t)(bytes)) : "memory")
#define MBARRIER_ARRIVE(mbar) \
    asm volatile("mbarrier.arrive.release.cta.shared.b64 _, [%0];" :: "r"((uint32_t)(mbar)) : "memory")
#define MBARRIER_WAIT_PARITY(mbar, parity) do {                                  \
    uint32_t _m = (uint32_t)(mbar);  uint32_t _p = (uint32_t)(parity);           \
    asm volatile(                                                                 \
        "{\n\t.reg .pred P1;\n\t"                                                 \
        "WL_%=:\n\t"                                                              \
        "mbarrier.try_wait.parity.acquire.cta.shared::cta.b64 P1, [%0], %1, 0x989680;\n\t" \
        "@P1 bra.uni WD_%=;\n\t"                                                  \
        "bra.uni WL_%=;\n\t"                                                      \
        "WD_%=:\n\t}"                                                             \
        :: "r"(_m), "r"(_p) : "memory");                                          \
} while (0)
#define TMA_LOAD_3D(saddr, tmap, cx, cy, cz, mbar) \
    asm volatile( \
        "cp.async.bulk.tensor.3d.shared::cta.global.tile.mbarrier::complete_tx::bytes " \
        "[%0], [%1, {%2, %3, %4}], [%5];" \
        :: "r"((uint32_t)(saddr)), "l"(tmap), "r"((int)(cx)), "r"((int)(cy)), "r"((int)(cz)), \
           "r"((uint32_t)(mbar)) : "memory")

// ===========================================================================
// Shared GEMM config: CTA 128x128, KT=32/stage, 3 stages, 128 thr (4 warps 64x64)
// ===========================================================================
static constexpr int BM = 128, BN = 128, KT = 32, STAGES = 3;
static constexpr int ABYT = BM * KT * 4;
static constexpr int BBYT = BN * KT * 4;
static constexpr int STB  = ABYT + BBYT;
static constexpr int SMEM_DYN = 1024 + STAGES * STB;   // 99328
static constexpr int NTHR = 128;

// Mainloop shared by both GEMM kernels. Computes 128x128 C tile into acc.
#define GEMM_MAINLOOP(tmA_, tmB_, zA_, zB_)                                         \
    if (tid == 0) {                                                                 \
        for (int s_ = 0; s_ < STAGES; s_++) {                                       \
            MBARRIER_INIT(FULLB(s_), 1);                                            \
            MBARRIER_INIT(EMPTYB(s_), 4);                                           \
        }                                                                           \
    }                                                                               \
    __syncthreads();                                                                \
    if (tid == 0) {                                                                 \
        for (int s_ = 0; s_ < STAGES; s_++) {                                       \
            MBARRIER_EXPECT_TX(FULLB(s_), STB);                                     \
            TMA_LOAD_3D(sb + s_ * STB,        &(tmA_), s_ * KT, m0, (zA_), FULLB(s_)); \
            TMA_LOAD_3D(sb + s_ * STB + ABYT, &(tmB_), s_ * KT, n0, (zB_), FULLB(s_)); \
        }                                                                           \
    }                                                                               \
    const uint32_t gx   = (uint32_t)gID << 4;                                       \
    const uint32_t rowA = (uint32_t)(wm * 64 + gID) * 128;                          \
    const uint32_t rowB = (uint32_t)(wn * 64 + gID) * 128;                          \
    int s = 0, ph = 0;                                                              \
    for (int kt = 0; kt < 32; kt++) {                                               \
        const uint32_t stg = sb + s * STB;                                          \
        MBARRIER_WAIT_PARITY(FULLB(s), ph);                                         \
        const uint32_t aBase = stg + rowA;                                          \
        const uint32_t bBase = stg + ABYT + rowB;                                   \
        _Pragma("unroll")                                                           \
        for (int kk = 0; kk < 4; kk++) {                                            \
            const uint32_t off0 = ((uint32_t)(kk * 32 + tig * 4)) ^ gx;             \
            const uint32_t off1 = off0 ^ 16u;                                       \
            uint32_t ua[4][4], ub[8][2];                                            \
            _Pragma("unroll")                                                       \
            for (int mi = 0; mi < 4; mi++) {                                        \
                ua[mi][0] = lds_u(aBase + mi * 2048 + off0);                        \
                ua[mi][1] = lds_u(aBase + mi * 2048 + 1024 + off0);                 \
                ua[mi][2] = lds_u(aBase + mi * 2048 + off1);                        \
                ua[mi][3] = lds_u(aBase + mi * 2048 + 1024 + off1);                 \
            }                                                                       \
            _Pragma("unroll")                                                       \
            for (int ni = 0; ni < 8; ni++) {                                        \
                ub[ni][0] = lds_u(bBase + ni * 1024 + off0);                        \
                ub[ni][1] = lds_u(bBase + ni * 1024 + off1);                        \
            }                                                                       \
            _Pragma("unroll")                                                       \
            for (int mi = 0; mi < 4; mi++)                                          \
                _Pragma("unroll")                                                   \
                for (int ni = 0; ni < 8; ni++)                                      \
                    asm volatile(                                                   \
                        "mma.sync.aligned.m16n8k8.row.col.f32.tf32.tf32.f32 "       \
                        "{%0,%1,%2,%3},{%4,%5,%6,%7},{%8,%9},{%0,%1,%2,%3};"        \
                        : "+f"(acc[mi][ni][0]), "+f"(acc[mi][ni][1]),               \
                          "+f"(acc[mi][ni][2]), "+f"(acc[mi][ni][3])                \
                        : "r"(ua[mi][0]), "r"(ua[mi][1]), "r"(ua[mi][2]), "r"(ua[mi][3]), \
                          "r"(ub[ni][0]), "r"(ub[ni][1]));                          \
        }                                                                           \
        __syncwarp();                                                               \
        if (lane == 0) MBARRIER_ARRIVE(EMPTYB(s));                                  \
        if (tid == 0 && kt + STAGES < 32) {                                         \
            MBARRIER_WAIT_PARITY(EMPTYB(s), ph);                                    \
            MBARRIER_EXPECT_TX(FULLB(s), STB);                                      \
            TMA_LOAD_3D(sb + s * STB,        &(tmA_), (kt + STAGES) * KT, m0, (zA_), FULLB(s)); \
            TMA_LOAD_3D(sb + s * STB + ABYT, &(tmB_), (kt + STAGES) * KT, n0, (zB_), FULLB(s)); \
        }                                                                           \
        if (++s == STAGES) { s = 0; ph ^= 1; }                                      \
    }                                                                               \
    __syncthreads();

// ===========================================================================
// Batched GEMM (no bias): C[z][M,N] = A[z] @ B[z]^T
// ===========================================================================
__global__ void __launch_bounds__(NTHR, 2)
gemm_tc(const __grid_constant__ CUtensorMap tmA,
        const __grid_constant__ CUtensorMap tmB,
        float* __restrict__ C, long sCz)
{
    extern __shared__ char dynraw[];
    __shared__ __align__(8) unsigned long long mb[2 * STAGES];
    uint32_t d0 = smem_u32(dynraw);
    uint32_t sb = (d0 + 1023u) & ~1023u;
    const int tid = threadIdx.x;
    const int warp = tid >> 5, lane = tid & 31;
    const int wm = warp & 1, wn = warp >> 1;
    const int gID = lane >> 2, tig = lane & 3;
    const int m0 = blockIdx.y * BM, n0 = blockIdx.x * BN, z = blockIdx.z;
    const uint32_t mbase = smem_u32(mb);
#define FULLB(s)  (mbase + 8 * (s))
#define EMPTYB(s) (mbase + 24 + 8 * (s))

    float acc[4][8][4];
#pragma unroll
    for (int mi = 0; mi < 4; mi++)
#pragma unroll
        for (int ni = 0; ni < 8; ni++)
#pragma unroll
            for (int e = 0; e < 4; e++) acc[mi][ni][e] = 0.0f;

    GEMM_MAINLOOP(tmA, tmB, z, z)

    float* ep = (float*)(dynraw + (sb - d0));
    const int P = 132;
#pragma unroll
    for (int mi = 0; mi < 4; mi++)
#pragma unroll
        for (int ni = 0; ni < 8; ni++) {
            const int r = wm * 64 + mi * 16 + gID;
            const int c = wn * 64 + ni * 8 + 2 * tig;
            *(float2*)(ep + r * P + c)       = make_float2(acc[mi][ni][0], acc[mi][ni][1]);
            *(float2*)(ep + (r + 8) * P + c) = make_float2(acc[mi][ni][2], acc[mi][ni][3]);
        }
    __syncthreads();
    float* Cz = C + (long)z * sCz;
#pragma unroll
    for (int it = 0; it < 32; it++) {
        const int idx = tid + it * NTHR;
        const int r = idx >> 5, c4 = (idx & 31) * 4;
        float4 v = *(float4*)(ep + r * P + c4);
        *(float4*)(Cz + (long)(m0 + r) * 1024 + n0 + c4) = v;
    }
#undef FULLB
#undef EMPTYB
}

// ===========================================================================
// Wide projection GEMM: C[M, 3072] = A[M,1024] @ W[3072,1024]^T + biasC
// n-tile section sec = n0>>10 routes to p0/p1/p2; trans_mask bit -> transposed
// per-batch write (B, DT, SEQ). Outputs rounded to tf32.
// ===========================================================================
__global__ void __launch_bounds__(NTHR, 2)
gemm_proj(const __grid_constant__ CUtensorMap tmA,
          const __grid_constant__ CUtensorMap tmB,
          float* __restrict__ p0, float* __restrict__ p1, float* __restrict__ p2,
          const float* __restrict__ biasC, uint32_t trans_mask)
{
    extern __shared__ char dynraw[];
    __shared__ __align__(8) unsigned long long mb[2 * STAGES];
    uint32_t d0 = smem_u32(dynraw);
    uint32_t sb = (d0 + 1023u) & ~1023u;
    const int tid = threadIdx.x;
    const int warp = tid >> 5, lane = tid & 31;
    const int wm = warp & 1, wn = warp >> 1;
    const int gID = lane >> 2, tig = lane & 3;
    const int m0 = blockIdx.y * BM, n0 = blockIdx.x * BN;
    const uint32_t mbase = smem_u32(mb);
#define FULLB(s)  (mbase + 8 * (s))
#define EMPTYB(s) (mbase + 24 + 8 * (s))

    float acc[4][8][4];
#pragma unroll
    for (int mi = 0; mi < 4; mi++)
#pragma unroll
        for (int ni = 0; ni < 8; ni++)
#pragma unroll
            for (int e = 0; e < 4; e++) acc[mi][ni][e] = 0.0f;

    GEMM_MAINLOOP(tmA, tmB, 0, 0)

    // bias + round
#pragma unroll
    for (int ni = 0; ni < 8; ni++) {
        const int nc = n0 + wn * 64 + ni * 8 + 2 * tig;
        const float b0 = __ldg(biasC + nc), b1 = __ldg(biasC + nc + 1);
#pragma unroll
        for (int mi = 0; mi < 4; mi++) {
            acc[mi][ni][0] = rnd_tf32(acc[mi][ni][0] + b0);
            acc[mi][ni][1] = rnd_tf32(acc[mi][ni][1] + b1);
            acc[mi][ni][2] = rnd_tf32(acc[mi][ni][2] + b0);
            acc[mi][ni][3] = rnd_tf32(acc[mi][ni][3] + b1);
        }
    }

    const int sec = n0 >> 10;
    const int n0l = n0 & 1023;
    float* dst = (sec == 0) ? p0 : (sec == 1) ? p1 : p2;
    const bool tr = (trans_mask >> sec) & 1u;
    float* ep = (float*)(dynraw + (sb - d0));

    if (!tr) {
        const int P = 132;
#pragma unroll
        for (int mi = 0; mi < 4; mi++)
#pragma unroll
            for (int ni = 0; ni < 8; ni++) {
                const int r = wm * 64 + mi * 16 + gID;
                const int c = wn * 64 + ni * 8 + 2 * tig;
                *(float2*)(ep + r * P + c)       = make_float2(acc[mi][ni][0], acc[mi][ni][1]);
                *(float2*)(ep + (r + 8) * P + c) = make_float2(acc[mi][ni][2], acc[mi][ni][3]);
            }
        __syncthreads();
#pragma unroll
        for (int it = 0; it < 32; it++) {
            const int idx = tid + it * NTHR;
            const int r = idx >> 5, c4 = (idx & 31) * 4;
            float4 v = *(float4*)(ep + r * P + c4);
            *(float4*)(dst + (long)(m0 + r) * 1024 + n0l + c4) = v;
        }
    } else {
        const int P = 129;
#pragma unroll
        for (int mi = 0; mi < 4; mi++)
#pragma unroll
            for (int ni = 0; ni < 8; ni++) {
                const int r = wm * 64 + mi * 16 + gID;
                const int c = wn * 64 + ni * 8 + 2 * tig;
                ep[r * P + c]           = acc[mi][ni][0];
                ep[r * P + c + 1]       = acc[mi][ni][1];
                ep[(r + 8) * P + c]     = acc[mi][ni][2];
                ep[(r + 8) * P + c + 1] = acc[mi][ni][3];
            }
        __syncthreads();
        const int b   = m0 >> 10;
        const int mlb = m0 & 1023;
#pragma unroll 8
        for (int it = 0; it < 128; it++) {
            const int idx = tid + it * NTHR;
            const int n = idx >> 7, m = idx & 127;
            dst[((long)b << 20) + (long)(n0l + n) * 1024 + (mlb + m)] = ep[m * P + n];
        }
    }
#undef FULLB
#undef EMPTYB
}

// ===========================================================================
// Pre-round to tf32
// ===========================================================================
__global__ void round_kernel(const float4* __restrict__ in, float4* __restrict__ out, long n4)
{
    long i = (long)blockIdx.x * blockDim.x + threadIdx.x;
    long stride = (long)gridDim.x * blockDim.x;
    for (; i < n4; i += stride) {
        float4 v = in[i];
        v.x = rnd_tf32(v.x); v.y = rnd_tf32(v.y);
        v.z = rnd_tf32(v.z); v.w = rnd_tf32(v.w);
        out[i] = v;
    }
}

struct Ptr6 { const float4* in[6]; };
__global__ void round6_kernel(Ptr6 p, float4* __restrict__ out, long n4each)
{
    const float4* in = p.in[blockIdx.y];
    float4* o = out + blockIdx.y * n4each;
    long i = (long)blockIdx.x * blockDim.x + threadIdx.x;
    long stride = (long)gridDim.x * blockDim.x;
    for (; i < n4each; i += stride) {
        float4 v = in[i];
        v.x = rnd_tf32(v.x); v.y = rnd_tf32(v.y);
        v.z = rnd_tf32(v.z); v.w = rnd_tf32(v.w);
        o[i] = v;
    }
}

__global__ void cat_bias(const float* __restrict__ a, const float* __restrict__ b,
                         const float* __restrict__ c, float* __restrict__ o)
{
    int i = blockIdx.x * 256 + threadIdx.x;   // 0..3071
    o[i] = (i < 1024) ? a[i] : (i < 2048) ? b[i - 1024] : c[i - 2048];
}

// ===========================================================================
// Two-stage mean pool
// ===========================================================================
__global__ void pool1_kernel(const float* __restrict__ src, float* __restrict__ part)
{
    int b = blockIdx.y, sp = blockIdx.z;
    int d = blockIdx.x * 256 + threadIdx.x;
    const float* p = src + ((long)b << 20) + ((long)sp << 17) + d;   // sp*128*1024
    float s = 0.f;
#pragma unroll 16
    for (int m = 0; m < 128; m++) s += p[m << 10];
    part[(((b << 3) + sp) << 10) + d] = s;
}
__global__ void pool2_kernel(const float* __restrict__ part, float* __restrict__ dst)
{
    int b = blockIdx.y;
    int d = blockIdx.x * 256 + threadIdx.x;
    float s = 0.f;
#pragma unroll
    for (int sp = 0; sp < 8; sp++) s += part[(((b << 3) + sp) << 10) + d];
    dst[(b << 10) + d] = s * (1.0f / 1024.0f);
}

// ===========================================================================
// Gate FFN + mask/softmax/transpose
// ===========================================================================
__global__ void ffn_kernel(const float* __restrict__ poolV, const float* __restrict__ poolT,
                           const float* __restrict__ w1, const float* __restrict__ b1,
                           const float* __restrict__ w2, const float* __restrict__ b2,
                           float* __restrict__ lout)
{
    __shared__ float x[2 * DT];
    __shared__ float red[HID];
    int b = blockIdx.x, t = threadIdx.x;
    for (int i = t; i < 2 * DT; i += HID)
        x[i] = (i < DT) ? poolV[b * DT + i] : poolT[b * DT + (i - DT)];
    __syncthreads();
    float acc = b1[t];
    const float* wr = w1 + (long)t * (2 * DT);
#pragma unroll 8
    for (int k = 0; k < 2 * DT; k++) acc += wr[k] * x[k];
    float h = fmaxf(acc, 0.0f);
    red[t] = h * w2[t];
    __syncthreads();
    for (int s = HID / 2; s > 0; s >>= 1) {
        if (t < s) red[t] += red[t + s];
        __syncthreads();
    }
    if (t == 0) lout[b] = 1.0f / (1.0f + expf(-(red[0] + b2[0])));
}

__device__ __forceinline__ float block_max(float v, float* red)
{
    int t = threadIdx.x;
    red[t] = v; __syncthreads();
    for (int s = 128; s > 0; s >>= 1) {
        if (t < s) red[t] = fmaxf(red[t], red[t + s]);
        __syncthreads();
    }
    float r = red[0]; __syncthreads();
    return r;
}
__device__ __forceinline__ float block_sum(float v, float* red)
{
    int t = threadIdx.x;
    red[t] = v; __syncthreads();
    for (int s = 128; s > 0; s >>= 1) {
        if (t < s) red[t] += red[t + s];
        __syncthreads();
    }
    float r = red[0]; __syncthreads();
    return r;
}

__global__ void mask_kernel(const float* __restrict__ S, const float* __restrict__ lv,
                            float* __restrict__ maskO)
{
    __shared__ float red[256];
    int t = threadIdx.x;
    long row = (long)blockIdx.y * SEQ + blockIdx.x;
    const float* p = S + row * SEQ;
    float x[4];
    float mx = -3.4e38f;
#pragma unroll
    for (int i = 0; i < 4; i++) {
        x[i] = p[t + i * 256] * INV_SQRT;
        mx = fmaxf(mx, x[i]);
    }
    mx = block_max(mx, red);
    float s = 0.f;
#pragma unroll
    for (int i = 0; i < 4; i++) s += expf(x[i] - mx);
    s = block_sum(s, red);
    float l = lv[blockIdx.y];
    float* o = maskO + row * SEQ;
#pragma unroll
    for (int i = 0; i < 4; i++)
        o[t + i * 256] = ((expf(x[i] - mx) / s) >= l) ? 1.0f : 0.0f;
}

__global__ void msoftmax_kernel(float* __restrict__ S, const float* __restrict__ maskM)
{
    __shared__ float red[256];
    int t = threadIdx.x;
    long row = (long)blockIdx.y * SEQ + blockIdx.x;
    float* p = S + row * SEQ;
    const float* mk = maskM + row * SEQ;
    float x[4];
    float mx = -3.4e38f;
#pragma unroll
    for (int i = 0; i < 4; i++) {
        int idx = t + i * 256;
        x[i] = (mk[idx] != 0.0f) ? p[idx] * INV_SQRT : NEG_INF_F;
        mx = fmaxf(mx, x[i]);
    }
    mx = block_max(mx, red);
    float s = 0.f;
#pragma unroll
    for (int i = 0; i < 4; i++) s += expf(x[i] - mx);
    s = block_sum(s, red);
#pragma unroll
    for (int i = 0; i < 4; i++)
        p[t + i * 256] = rnd_tf32(expf(x[i] - mx) / s);
}

__global__ void transpose_kernel(const float* __restrict__ in, float* __restrict__ out)
{
    __shared__ float tile[32][33];
    long base = (long)blockIdx.z << 20;
    int m = blockIdx.y * 32 + threadIdx.y;
    int n = blockIdx.x * 32 + threadIdx.x;
    tile[threadIdx.y][threadIdx.x] = in[base + (long)m * SEQ + n];
    __syncthreads();
    int n2 = blockIdx.x * 32 + threadIdx.y;
    int m2 = blockIdx.y * 32 + threadIdx.x;
    out[base + (long)n2 * SEQ + m2] = tile[threadIdx.x][threadIdx.y];
}

// ===========================================================================
// Host side
// ===========================================================================
typedef CUresult (*PFN_encodeTiled)(CUtensorMap*, CUtensorMapDataType, cuuint32_t, void*,
                                    const cuuint64_t*, const cuuint64_t*, const cuuint32_t*,
                                    const cuuint32_t*, CUtensorMapInterleave, CUtensorMapSwizzle,
                                    CUtensorMapL2promotion, CUtensorMapFloatOOBfill);
static PFN_encodeTiled g_enc = nullptr;

static void enc3d(CUtensorMap* tm, const void* p, long K, long R, long Z)
{
    cuuint64_t dims[3] = {(cuuint64_t)K, (cuuint64_t)R, (cuuint64_t)Z};
    cuuint64_t str[2]  = {(cuuint64_t)(K * 4), (cuuint64_t)(K * R * 4)};
    cuuint32_t box[3]  = {(cuuint32_t)KT, 128, 1};
    cuuint32_t es[3]   = {1, 1, 1};
    g_enc(tm, CU_TENSOR_MAP_DATA_TYPE_FLOAT32, 3, (void*)p, dims, str, box, es,
          CU_TENSOR_MAP_INTERLEAVE_NONE, CU_TENSOR_MAP_SWIZZLE_128B,
          CU_TENSOR_MAP_L2_PROMOTION_L2_128B, CU_TENSOR_MAP_FLOAT_OOB_FILL_NONE);
}

extern "C" void kernel_launch(void* const* d_in, const int* in_sizes, int n_in,
                              void* d_out, int out_size)
{
    (void)in_sizes; (void)n_in; (void)out_size;

    const float* oV     = (const float*)d_in[0];
    const float* oT     = (const float*)d_in[1];
    const float* Wq_v_w = (const float*)d_in[2];
    const float* Wq_v_b = (const float*)d_in[3];
    const float* Wk_t_w = (const float*)d_in[4];
    const float* Wk_t_b = (const float*)d_in[5];
    const float* Wv_t_w = (const float*)d_in[6];
    const float* Wv_t_b = (const float*)d_in[7];
    const float* Wq_t_w = (const float*)d_in[8];
    const float* Wq_t_b = (const float*)d_in[9];
    const float* Wk_v_w = (const float*)d_in[10];
    const float* Wk_v_b = (const float*)d_in[11];
    const float* Wv_v_w = (const float*)d_in[12];
    const float* Wv_v_b = (const float*)d_in[13];
    const float* ffn1_w = (const float*)d_in[14];
    const float* ffn1_b = (const float*)d_in[15];
    const float* ffn2_w = (const float*)d_in[16];
    const float* ffn2_b = (const float*)d_in[17];

    float* out_vt = (float*)d_out;
    float* out_tv = out_vt + ELEM1;
    float* maskO  = out_vt + 2 * ELEM1;

    static float* scr = nullptr;
    if (!scr) cudaGetSymbolAddress((void**)&scr, g_scr);
    if (!g_enc) {
        void* p = nullptr;
        cudaDriverEntryPointQueryResult st;
        cudaGetDriverEntryPoint("cuTensorMapEncodeTiled", &p, cudaEnableDefault, &st);
        g_enc = (PFN_encodeTiled)p;
    }
    static bool attr_done = false;
    if (!attr_done) {
        cudaFuncSetAttribute(gemm_tc,   cudaFuncAttributeMaxDynamicSharedMemorySize, SMEM_DYN);
        cudaFuncSetAttribute(gemm_proj, cudaFuncAttributeMaxDynamicSharedMemorySize, SMEM_DYN);
        attr_done = true;
    }

    float* Qv    = scr + 0 * ELEM1;
    float* Kt    = scr + 1 * ELEM1;
    float* VtT   = scr + 2 * ELEM1;   // (B, DT, SEQ)
    float* Qt    = scr + 3 * ELEM1;
    float* Kv    = scr + 4 * ELEM1;
    float* VvT   = scr + 5 * ELEM1;   // (B, DT, SEQ)
    float* Ssc   = scr + 6 * ELEM1;
    float* maskT = scr + 7 * ELEM1;
    float* oVr   = scr + 8 * ELEM1;
    float* oTr   = scr + 9 * ELEM1;
    float* Wr    = scr + 10 * ELEM1;             // 6 MB-floats: [Wq_v,Wk_v,Wv_v][Wk_t,Wv_t,Wq_t]
    float* poolV = Wr + 6L * DT * DT;
    float* poolT = poolV + BATCH * DT;
    float* lv    = poolT + BATCH * DT;
    float* partV = lv + 64;
    float* partT = partV + 8 * BATCH * 1024;
    float* biasV = partT + 8 * BATCH * 1024;
    float* biasT = biasV + 3072;

    // 0) pre-round GEMM inputs
    const long N4BIG = ELEM1 / 4;
    round_kernel<<<2048, 256>>>((const float4*)oV, (float4*)oVr, N4BIG);
    round_kernel<<<2048, 256>>>((const float4*)oT, (float4*)oTr, N4BIG);
    Ptr6 wp;
    wp.in[0] = (const float4*)Wq_v_w;  wp.in[1] = (const float4*)Wk_v_w;
    wp.in[2] = (const float4*)Wv_v_w;  wp.in[3] = (const float4*)Wk_t_w;
    wp.in[4] = (const float4*)Wv_t_w;  wp.in[5] = (const float4*)Wq_t_w;
    round6_kernel<<<dim3(256, 6), 256>>>(wp, (float4*)Wr, (long)DT * DT / 4);
    cat_bias<<<12, 256>>>(Wq_v_b, Wk_v_b, Wv_v_b, biasV);
    cat_bias<<<12, 256>>>(Wk_t_b, Wv_t_b, Wq_t_b, biasT);

    // 1) pools + gate (two-stage, 512 CTAs)
    pool1_kernel<<<dim3(4, BATCH, 8), 256>>>(oV, partV);
    pool1_kernel<<<dim3(4, BATCH, 8), 256>>>(oT, partT);
    pool2_kernel<<<dim3(4, BATCH), 256>>>(partV, poolV);
    pool2_kernel<<<dim3(4, BATCH), 256>>>(partT, poolT);
    ffn_kernel<<<BATCH, HID>>>(poolV, poolT, ffn1_w, ffn1_b, ffn2_w, ffn2_b, lv);

    CUtensorMap tA, tB;
    const dim3 gw(24, 128, 1);    // wide projections: N=3072
    const dim3 gb(8, 8, BATCH);

    // 2) projections: 2 wide GEMMs
    enc3d(&tA, oVr, DT, BATCH * SEQ, 1);
    enc3d(&tB, Wr, DT, 3 * DT, 1);
    gemm_proj<<<gw, NTHR, SMEM_DYN>>>(tA, tB, Qv, Kv, VvT, biasV, 0b100u);

    enc3d(&tA, oTr, DT, BATCH * SEQ, 1);
    enc3d(&tB, Wr + 3L * DT * DT, DT, 3 * DT, 1);
    gemm_proj<<<gw, NTHR, SMEM_DYN>>>(tA, tB, Kt, VtT, Qt, biasT, 0b010u);

    const long S1 = (long)SEQ * SEQ;

    // 3) sim -> mask -> maskT
    enc3d(&tA, oVr, DT, SEQ, BATCH);
    enc3d(&tB, oTr, DT, SEQ, BATCH);
    gemm_tc<<<gb, NTHR, SMEM_DYN>>>(tA, tB, Ssc, S1);
    mask_kernel<<<dim3(SEQ, BATCH), 256>>>(Ssc, lv, maskO);
    transpose_kernel<<<dim3(32, 32, BATCH), dim3(32, 32)>>>(maskO, maskT);

    // 4) V->T attention
    enc3d(&tA, Qv, DT, SEQ, BATCH);
    enc3d(&tB, Kt, DT, SEQ, BATCH);
    gemm_tc<<<gb, NTHR, SMEM_DYN>>>(tA, tB, Ssc, S1);
    msoftmax_kernel<<<dim3(SEQ, BATCH), 256>>>(Ssc, maskO);
    enc3d(&tA, Ssc, SEQ, SEQ, BATCH);
    enc3d(&tB, VtT, SEQ, DT, BATCH);
    gemm_tc<<<gb, NTHR, SMEM_DYN>>>(tA, tB, out_vt, S1);

    // 5) T->V attention
    enc3d(&tA, Qt, DT, SEQ, BATCH);
    enc3d(&tB, Kv, DT, SEQ, BATCH);
    gemm_tc<<<gb, NTHR, SMEM_DYN>>>(tA, tB, Ssc, S1);
    msoftmax_kernel<<<dim3(SEQ, BATCH), 256>>>(Ssc, maskT);
    enc3d(&tA, Ssc, SEQ, SEQ, BATCH);
    enc3d(&tB, VvT, SEQ, DT, BATCH);
    gemm_tc<<<gb, NTHR, SMEM_DYN>>>(tA, tB, out_tv, S1);
}